// round 7
// baseline (speedup 1.0000x reference)
#include <cuda_runtime.h>
#include <math.h>

#define Nn   8000
#define NPc  1000
#define Bc   8
#define Fc   1000
#define HCc  32
#define TRIc 499500
#define HIDc 128
#define EPSc 1e-5f
#define HPLANE (Bc * NPc * HCc)   // 256000 floats per h plane

// ---------------- persistent scratch ----------------
__device__ int    g_bar[32];                    // monotonic 2-block barrier counters
__device__ float2 g_edge[16 * 10000];           // per-block CSR copies
__device__ float  g_hbuf[2 * HPLANE];           // double-buffered h (layers 0,1)
__device__ float  g_emb[Bc * 96];
__device__ float  g_y1[Bc * HIDc];

// monotonic 2-block barrier (replay-safe, never reset)
__device__ __forceinline__ void gbar2(int slot) {
    __syncthreads();
    if (threadIdx.x == 0) {
        __threadfence();
        int r = atomicAdd(&g_bar[slot], 1);
        int target = (r / 2 + 1) * 2;
        while (atomicAdd(&g_bar[slot], 0) < target) { }
    }
    __syncthreads();
}

// ---------------- cheb helpers ----------------
__device__ __forceinline__ float gat16(const float* __restrict__ S,
                                       const float2* __restrict__ gE,
                                       const int* __restrict__ sRow,
                                       int d, int ch) {
    int i0 = sRow[d], i1 = sRow[d + 1];
    float s = 0.f;
#pragma unroll 2
    for (int i = i0; i < i1; i++) {
        float2 ed = __ldcg(&gE[i]);
        s = fmaf(ed.y, S[(__float_as_int(ed.x) << 4) + ch], s);
    }
    return s;
}

// v = dot(h_prev[d][0:32], W_k[:, ch0+ch]) using half-warp shuffles
__device__ __forceinline__ float vdot(const float* __restrict__ hrow,
                                      const float* __restrict__ sWk, int ch) {
    float hlo = __ldcg(hrow + ch);
    float hhi = __ldcg(hrow + 16 + ch);
    float v = 0.f;
#pragma unroll
    for (int j = 0; j < 16; j++) {
        v = fmaf(__shfl_sync(0xFFFFFFFFu, hlo, j, 16), sWk[j * 16 + ch], v);
        v = fmaf(__shfl_sync(0xFFFFFFFFu, hhi, j, 16), sWk[(j + 16) * 16 + ch], v);
    }
    return v;
}

// ---------------- one ChebConv layer, fully in-block ----------------
__device__ void run_layer(int L, int b, int ch0, int ch, int t,
                          float* sA, float* sB, const float* sW,
                          const int* sRow, const float2* gE,
                          const float* __restrict__ cw0,   // layer-0 weight planes, else unused
                          const float* __restrict__ cbL)
{
    const float* hprev = g_hbuf + (L - 1) * HPLANE + b * NPc * HCc;  // valid for L>0

    // init: A := v4
    for (int d = t >> 4; d < NPc; d += 64) {
        float v = (L == 0) ? __ldg(cw0 + 4 * Fc * HCc + d * HCc + ch0 + ch)
                           : vdot(hprev + d * HCc, sW + 4 * 512, ch);
        sA[(d << 4) + ch] = v;
    }
    __syncthreads();
    // k=3: B := v3 + 2 G(A)
    for (int d = t >> 4; d < NPc; d += 64) {
        float v = (L == 0) ? __ldg(cw0 + 3 * Fc * HCc + d * HCc + ch0 + ch)
                           : vdot(hprev + d * HCc, sW + 3 * 512, ch);
        sB[(d << 4) + ch] = fmaf(2.f, gat16(sA, gE, sRow, d, ch), v);
    }
    __syncthreads();
    // k=2: A := v2 + 2 G(B) - A
    for (int d = t >> 4; d < NPc; d += 64) {
        float v = (L == 0) ? __ldg(cw0 + 2 * Fc * HCc + d * HCc + ch0 + ch)
                           : vdot(hprev + d * HCc, sW + 2 * 512, ch);
        sA[(d << 4) + ch] = fmaf(2.f, gat16(sB, gE, sRow, d, ch), v) - sA[(d << 4) + ch];
    }
    __syncthreads();
    // k=1: B := v1 + 2 G(A) - B
    for (int d = t >> 4; d < NPc; d += 64) {
        float v = (L == 0) ? __ldg(cw0 + 1 * Fc * HCc + d * HCc + ch0 + ch)
                           : vdot(hprev + d * HCc, sW + 1 * 512, ch);
        sB[(d << 4) + ch] = fmaf(2.f, gat16(sA, gE, sRow, d, ch), v) - sB[(d << 4) + ch];
    }
    __syncthreads();
    // final: h = tanh(v0 + G(B) - A + bias); pool; store h for next layer
    float bl = __ldg(cbL + ch0 + ch);
    float pool = 0.f;
    for (int d = t >> 4; d < NPc; d += 64) {
        float v = (L == 0) ? __ldg(cw0 + 0 * Fc * HCc + d * HCc + ch0 + ch)
                           : vdot(hprev + d * HCc, sW + 0 * 512, ch);
        float h = tanhf(v + gat16(sB, gE, sRow, d, ch) - sA[(d << 4) + ch] + bl);
        pool += h;
        if (L < 2) g_hbuf[L * HPLANE + b * NPc * HCc + d * HCc + ch0 + ch] = h;
    }
    atomicAdd(&g_emb[b * 96 + L * 32 + ch0 + ch], pool);
    __syncthreads();
}

// ---------------- the cheb kernel: 16 blocks, whole GNN ----------------
// smem floats: sA[16000] sB[16000] sW[2560] scan[1024] deg[1000] cnt[1000] row[1001] cur[1000]
#define SM_A    0
#define SM_B    16000
#define SM_W    32000
#define SM_SCAN 34560
#define SM_DEG  35584
#define SM_CNT  36584
#define SM_ROW  37584
#define SM_CUR  38585
#define SM_TOT  39592

__global__ void __launch_bounds__(1024, 1)
cheb_kernel(const int* __restrict__ src, const int* __restrict__ dst, int E,
            const float* __restrict__ cw0, const float* __restrict__ cb0,
            const float* __restrict__ cw1, const float* __restrict__ cb1,
            const float* __restrict__ cw2, const float* __restrict__ cb2)
{
    extern __shared__ float sm[];
    float* sA = sm + SM_A;
    float* sB = sm + SM_B;
    float* sW = sm + SM_W;
    int* sScan = (int*)(sm + SM_SCAN);
    int* sDeg  = (int*)(sm + SM_DEG);   // src (out) degree -> edge weights
    int* sCnt  = (int*)(sm + SM_CNT);   // dst (in) counts  -> CSR rowptr
    int* sRow  = (int*)(sm + SM_ROW);
    int* sCur  = (int*)(sm + SM_CUR);

    const int t = threadIdx.x, blk = blockIdx.x;
    const int b = blk >> 1, r = blk & 1;
    const int ch = t & 15, ch0 = r * 16;
    const int EB = E / Bc;
    const int e0 = b * EB;
    float2* gE = g_edge + blk * EB;

    // zero own pooled-emb columns (48 per block, disjoint across blocks)
    if (t < 48) {
        int L = t / 16, cc = t % 16;
        g_emb[b * 96 + L * 32 + ch0 + cc] = 0.f;
    }

    // ---- in-block CSR build for this batch ----
    for (int i = t; i < NPc; i += 1024) { sDeg[i] = 0; sCnt[i] = 0; }
    __syncthreads();
    for (int e = e0 + t; e < e0 + EB; e += 1024) {
        atomicAdd(&sDeg[__ldg(src + e) - b * NPc], 1);
        atomicAdd(&sCnt[__ldg(dst + e) - b * NPc], 1);
    }
    __syncthreads();
    {   // exclusive scan of sCnt (dst counts) -> sRow/sCur
        int c = (t < NPc) ? sCnt[t] : 0;
        sScan[t] = c;
        __syncthreads();
        for (int off = 1; off < 1024; off <<= 1) {
            int v = (t >= off) ? sScan[t - off] : 0;
            __syncthreads();
            sScan[t] += v;
            __syncthreads();
        }
        if (t < NPc) { sRow[t] = sScan[t] - c; sCur[t] = sScan[t] - c; }
        if (t == 0) sRow[NPc] = sScan[1023];
    }
    __syncthreads();
    for (int e = e0 + t; e < e0 + EB; e += 1024) {
        int s_ = __ldg(src + e) - b * NPc;
        int d_ = __ldg(dst + e) - b * NPc;
        int ds = sDeg[s_], dd = sDeg[d_];
        float w = (ds > 0 && dd > 0) ? -rsqrtf((float)ds) * rsqrtf((float)dd) : 0.f;
        int pos = atomicAdd(&sCur[d_], 1);
        gE[pos] = make_float2(__int_as_float(s_), w);
    }
    __threadfence();
    __syncthreads();

    // ---- layer 0 (identity input; v-tables are the cw0 planes) ----
    run_layer(0, b, ch0, ch, t, sA, sB, sW, sRow, gE, cw0, cb0);

    // exchange h halves, load layer-1 weights
    __threadfence();
    gbar2(b * 2 + 0);
    for (int idx = t; idx < 5 * 512; idx += 1024) {
        int cc = idx & 15, j = (idx >> 4) & 31, k = idx >> 9;
        sW[idx] = __ldg(cw1 + k * 1024 + j * 32 + ch0 + cc);
    }
    __syncthreads();
    run_layer(1, b, ch0, ch, t, sA, sB, sW, sRow, gE, nullptr, cb1);

    __threadfence();
    gbar2(b * 2 + 1);
    for (int idx = t; idx < 5 * 512; idx += 1024) {
        int cc = idx & 15, j = (idx >> 4) & 31, k = idx >> 9;
        sW[idx] = __ldg(cw2 + k * 1024 + j * 32 + ch0 + cc);
    }
    __syncthreads();
    run_layer(2, b, ch0, ch, t, sA, sB, sW, sRow, gE, nullptr, cb2);
}

// ---------------- GEMM kernel: fused triu+fbn + W1 stream ----------------
#define GNB   444
#define GCH   256
#define GNCH  ((TRIc + GCH - 1) / GCH)   // 1952

__global__ void __launch_bounds__(256, 3)
gemm_kernel(const float* __restrict__ x, const float* __restrict__ W1,
            const float* __restrict__ bng, const float* __restrict__ bnb)
{
    __shared__ float sfb[GCH * 8];
    __shared__ float sred[4096];
    int t = threadIdx.x, wp = t >> 5, l = t & 31;
    float acc[Bc][4];
#pragma unroll
    for (int b = 0; b < Bc; b++)
#pragma unroll
        for (int q = 0; q < 4; q++) acc[b][q] = 0.f;

    for (int c = blockIdx.x; c < GNCH; c += GNB) {
        int fbase = c * GCH;
        __syncthreads();
        // phase A: fbn for 256 rows (1 per thread)
        {
            int f = fbase + t;
            float res[Bc];
            if (f < TRIc) {
                float disc = 3996001.0f - 8.0f * (float)f;
                float sq = sqrtf(fmaxf(disc, 0.f));
                int i = (int)((1999.0f - sq) * 0.5f);
                i = max(0, min(i, Fc - 2));
                while (i + 1 <= Fc - 2 && (((long long)(i + 1) * (1999 - (i + 1))) >> 1) <= (long long)f) i++;
                while (i > 0 && (((long long)i * (1999 - i)) >> 1) > (long long)f) i--;
                int Si = (int)(((long long)i * (1999 - i)) >> 1);
                int j = i + 1 + (f - Si);
                float v[Bc]; float m = 0.f;
#pragma unroll
                for (int b = 0; b < Bc; b++) {
                    v[b] = __ldg(x + ((size_t)(b * Fc + i) * Fc + j));
                    m += v[b];
                }
                m *= 0.125f;
                float var = 0.f;
#pragma unroll
                for (int b = 0; b < Bc; b++) { float dd = v[b] - m; var = fmaf(dd, dd, var); }
                var *= 0.125f;
                float sc = rsqrtf(var + EPSc) * __ldg(bng + f);
                float sh = __ldg(bnb + f);
#pragma unroll
                for (int b = 0; b < Bc; b++) res[b] = (v[b] - m) * sc + sh;
            } else {
#pragma unroll
                for (int b = 0; b < Bc; b++) res[b] = 0.f;
            }
            *(float4*)&sfb[t * 8]     = make_float4(res[0], res[1], res[2], res[3]);
            *(float4*)&sfb[t * 8 + 4] = make_float4(res[4], res[5], res[6], res[7]);
        }
        __syncthreads();
        // phase B: warp wp streams rows [wp*32, wp*32+32), batch-4 prefetch
        int r0 = wp * 32;
#pragma unroll 2
        for (int rb = 0; rb < 32; rb += 4) {
            float4 w[4];
#pragma unroll
            for (int u = 0; u < 4; u++) {
                int f2 = min(fbase + r0 + rb + u, TRIc - 1);
                w[u] = __ldcs((const float4*)(W1 + (size_t)f2 * HIDc + l * 4));
            }
#pragma unroll
            for (int u = 0; u < 4; u++) {
                int fl = r0 + rb + u;
                float4 f0 = *(const float4*)&sfb[fl * 8];
                float4 f1 = *(const float4*)&sfb[fl * 8 + 4];
                acc[0][0] = fmaf(f0.x, w[u].x, acc[0][0]); acc[0][1] = fmaf(f0.x, w[u].y, acc[0][1]);
                acc[0][2] = fmaf(f0.x, w[u].z, acc[0][2]); acc[0][3] = fmaf(f0.x, w[u].w, acc[0][3]);
                acc[1][0] = fmaf(f0.y, w[u].x, acc[1][0]); acc[1][1] = fmaf(f0.y, w[u].y, acc[1][1]);
                acc[1][2] = fmaf(f0.y, w[u].z, acc[1][2]); acc[1][3] = fmaf(f0.y, w[u].w, acc[1][3]);
                acc[2][0] = fmaf(f0.z, w[u].x, acc[2][0]); acc[2][1] = fmaf(f0.z, w[u].y, acc[2][1]);
                acc[2][2] = fmaf(f0.z, w[u].z, acc[2][2]); acc[2][3] = fmaf(f0.z, w[u].w, acc[2][3]);
                acc[3][0] = fmaf(f0.w, w[u].x, acc[3][0]); acc[3][1] = fmaf(f0.w, w[u].y, acc[3][1]);
                acc[3][2] = fmaf(f0.w, w[u].z, acc[3][2]); acc[3][3] = fmaf(f0.w, w[u].w, acc[3][3]);
                acc[4][0] = fmaf(f1.x, w[u].x, acc[4][0]); acc[4][1] = fmaf(f1.x, w[u].y, acc[4][1]);
                acc[4][2] = fmaf(f1.x, w[u].z, acc[4][2]); acc[4][3] = fmaf(f1.x, w[u].w, acc[4][3]);
                acc[5][0] = fmaf(f1.y, w[u].x, acc[5][0]); acc[5][1] = fmaf(f1.y, w[u].y, acc[5][1]);
                acc[5][2] = fmaf(f1.y, w[u].z, acc[5][2]); acc[5][3] = fmaf(f1.y, w[u].w, acc[5][3]);
                acc[6][0] = fmaf(f1.z, w[u].x, acc[6][0]); acc[6][1] = fmaf(f1.z, w[u].y, acc[6][1]);
                acc[6][2] = fmaf(f1.z, w[u].z, acc[6][2]); acc[6][3] = fmaf(f1.z, w[u].w, acc[6][3]);
                acc[7][0] = fmaf(f1.w, w[u].x, acc[7][0]); acc[7][1] = fmaf(f1.w, w[u].y, acc[7][1]);
                acc[7][2] = fmaf(f1.w, w[u].z, acc[7][2]); acc[7][3] = fmaf(f1.w, w[u].w, acc[7][3]);
            }
        }
    }
    __syncthreads();
    // tree reduce 8 warps -> 1
    for (int half = 4; half >= 1; half >>= 1) {
        if (wp >= half && wp < 2 * half) {
            float* reg = sred + (wp - half) * 1024;
#pragma unroll
            for (int b = 0; b < Bc; b++)
                *(float4*)&reg[b * HIDc + l * 4] =
                    make_float4(acc[b][0], acc[b][1], acc[b][2], acc[b][3]);
        }
        __syncthreads();
        if (wp < half) {
            float* reg = sred + wp * 1024;
#pragma unroll
            for (int b = 0; b < Bc; b++) {
                float4 z = *(const float4*)&reg[b * HIDc + l * 4];
                acc[b][0] += z.x; acc[b][1] += z.y; acc[b][2] += z.z; acc[b][3] += z.w;
            }
        }
        __syncthreads();
    }
    if (wp == 0) {
#pragma unroll
        for (int b = 0; b < Bc; b++)
#pragma unroll
            for (int q = 0; q < 4; q++)
                atomicAdd(&g_y1[b * HIDc + l * 4 + q], acc[b][q]);
    }
}

// ---------------- head: hbn output + MLP + log-softmax ----------------
__global__ void head_kernel(const float* __restrict__ bnhg, const float* __restrict__ bnhb,
                            const float* __restrict__ b1,
                            const float* __restrict__ g1, const float* __restrict__ be1,
                            const float* __restrict__ W2, const float* __restrict__ b2,
                            const float* __restrict__ g2, const float* __restrict__ be2,
                            const float* __restrict__ W3, const float* __restrict__ b3,
                            const float* __restrict__ g3, const float* __restrict__ be3,
                            const float* __restrict__ W4, const float* __restrict__ b4,
                            float* __restrict__ out) {
    __shared__ float a1[8 * 128];
    __shared__ float a2[8 * 64];
    __shared__ float a3[8 * 64];
    __shared__ float lg[16];
    int t = threadIdx.x;

    if (t < 96) {
        float e[Bc]; float m = 0.f;
#pragma unroll
        for (int b = 0; b < Bc; b++) { e[b] = __ldcg(&g_emb[b * 96 + t]) * (1.f / (float)NPc); m += e[b]; }
        m *= 0.125f;
        float v = 0.f;
#pragma unroll
        for (int b = 0; b < Bc; b++) { float dd = e[b] - m; v = fmaf(dd, dd, v); }
        v *= 0.125f;
        float sc = rsqrtf(v + EPSc) * __ldg(bnhg + t);
        float sh = __ldg(bnhb + t);
#pragma unroll
        for (int b = 0; b < Bc; b++) out[16 + b * 96 + t] = (e[b] - m) * sc + sh;
    }

    for (int idx = t; idx < 1024; idx += 256) a1[idx] = __ldcg(&g_y1[idx]) + __ldg(&b1[idx & 127]);
    __syncthreads();
    if (t < 128) {
        float m = 0.f;
#pragma unroll
        for (int b = 0; b < Bc; b++) m += a1[b * 128 + t];
        m *= 0.125f;
        float v = 0.f;
#pragma unroll
        for (int b = 0; b < Bc; b++) { float dd = a1[b * 128 + t] - m; v = fmaf(dd, dd, v); }
        v *= 0.125f;
        float sc = rsqrtf(v + EPSc) * __ldg(g1 + t);
        float sh = __ldg(be1 + t);
#pragma unroll
        for (int b = 0; b < Bc; b++) {
            float z = (a1[b * 128 + t] - m) * sc + sh;
            a1[b * 128 + t] = z > 0.f ? z : 0.f;
        }
    }
    __syncthreads();
    for (int idx = t; idx < 512; idx += 256) {
        int b = idx >> 6, h = idx & 63;
        float s = __ldg(b2 + h);
        for (int j = 0; j < 128; j++) s = fmaf(a1[b * 128 + j], __ldg(W2 + j * 64 + h), s);
        a2[idx] = s;
    }
    __syncthreads();
    if (t < 64) {
        float m = 0.f;
#pragma unroll
        for (int b = 0; b < Bc; b++) m += a2[b * 64 + t];
        m *= 0.125f;
        float v = 0.f;
#pragma unroll
        for (int b = 0; b < Bc; b++) { float dd = a2[b * 64 + t] - m; v = fmaf(dd, dd, v); }
        v *= 0.125f;
        float sc = rsqrtf(v + EPSc) * __ldg(g2 + t);
        float sh = __ldg(be2 + t);
#pragma unroll
        for (int b = 0; b < Bc; b++) {
            float z = (a2[b * 64 + t] - m) * sc + sh;
            a2[b * 64 + t] = z > 0.f ? z : 0.f;
        }
    }
    __syncthreads();
    for (int idx = t; idx < 512; idx += 256) {
        int b = idx >> 6, h = idx & 63;
        float s = __ldg(b3 + h);
        for (int j = 0; j < 64; j++) s = fmaf(a2[b * 64 + j], __ldg(W3 + j * 64 + h), s);
        a3[idx] = s;
    }
    __syncthreads();
    if (t < 64) {
        float m = 0.f;
#pragma unroll
        for (int b = 0; b < Bc; b++) m += a3[b * 64 + t];
        m *= 0.125f;
        float v = 0.f;
#pragma unroll
        for (int b = 0; b < Bc; b++) { float dd = a3[b * 64 + t] - m; v = fmaf(dd, dd, v); }
        v *= 0.125f;
        float sc = rsqrtf(v + EPSc) * __ldg(g3 + t);
        float sh = __ldg(be3 + t);
#pragma unroll
        for (int b = 0; b < Bc; b++) {
            float z = (a3[b * 64 + t] - m) * sc + sh;
            a3[b * 64 + t] = z > 0.f ? z : 0.f;
        }
    }
    __syncthreads();
    if (t < 16) {
        int b = t >> 1, c = t & 1;
        float s = __ldg(b4 + c);
        for (int j = 0; j < 64; j++) s = fmaf(a3[b * 64 + j], __ldg(W4 + j * 2 + c), s);
        lg[t] = s;
    }
    __syncthreads();
    if (t < 8) {
        float l0 = lg[t * 2], l1 = lg[t * 2 + 1];
        float m = fmaxf(l0, l1);
        float lse = m + logf(expf(l0 - m) + expf(l1 - m));
        out[t * 2 + 0] = l0 - lse;
        out[t * 2 + 1] = l1 - lse;
    }
}

// ---------------- host driver ----------------
extern "C" void kernel_launch(void* const* d_in, const int* in_sizes, int n_in,
                              void* d_out, int out_size) {
    const float* x    = (const float*)d_in[0];
    const int*   ei   = (const int*)d_in[1];
    int E = in_sizes[1] / 2;
    const int* src = ei;
    const int* dst = ei + E;
    const float* cw0  = (const float*)d_in[3];
    const float* cb0  = (const float*)d_in[4];
    const float* cw1  = (const float*)d_in[5];
    const float* cb1  = (const float*)d_in[6];
    const float* cw2  = (const float*)d_in[7];
    const float* cb2  = (const float*)d_in[8];
    const float* bnhg = (const float*)d_in[9];
    const float* bnhb = (const float*)d_in[10];
    const float* bng  = (const float*)d_in[11];
    const float* bnb  = (const float*)d_in[12];
    const float* w1   = (const float*)d_in[13];
    const float* b1   = (const float*)d_in[14];
    const float* g1   = (const float*)d_in[15];
    const float* be1  = (const float*)d_in[16];
    const float* W2   = (const float*)d_in[17];
    const float* b2   = (const float*)d_in[18];
    const float* g2   = (const float*)d_in[19];
    const float* be2  = (const float*)d_in[20];
    const float* W3   = (const float*)d_in[21];
    const float* b3   = (const float*)d_in[22];
    const float* g3   = (const float*)d_in[23];
    const float* be3  = (const float*)d_in[24];
    const float* W4   = (const float*)d_in[25];
    const float* b4   = (const float*)d_in[26];
    float* out = (float*)d_out;

    void* y1ptr = nullptr;
    cudaGetSymbolAddress(&y1ptr, g_y1);

    // fork the GEMM branch onto a second stream
    cudaStream_t s2 = 0;
    cudaEvent_t evF = 0, evJ = 0;
    bool forked = (cudaStreamCreateWithFlags(&s2, cudaStreamNonBlocking) == cudaSuccess) &&
                  (cudaEventCreateWithFlags(&evF, cudaEventDisableTiming) == cudaSuccess) &&
                  (cudaEventCreateWithFlags(&evJ, cudaEventDisableTiming) == cudaSuccess);
    if (!forked) s2 = 0;

    if (forked) {
        cudaEventRecord(evF, 0);
        cudaStreamWaitEvent(s2, evF, 0);
    }
    cudaMemsetAsync(y1ptr, 0, Bc * HIDc * sizeof(float), s2);
    gemm_kernel<<<GNB, 256, 0, s2>>>(x, w1, bng, bnb);
    if (forked) cudaEventRecord(evJ, s2);

    // cheb branch (stream 0)
    cudaFuncSetAttribute(cheb_kernel, cudaFuncAttributeMaxDynamicSharedMemorySize,
                         SM_TOT * (int)sizeof(float));
    cheb_kernel<<<16, 1024, SM_TOT * sizeof(float)>>>(src, dst, E,
                                                      cw0, cb0, cw1, cb1, cw2, cb2);

    if (forked) cudaStreamWaitEvent(0, evJ, 0);
    head_kernel<<<1, 256>>>(bnhg, bnhb, b1, g1, be1, W2, b2, g2, be2,
                            W3, b3, g3, be3, W4, b4, out);
}

// round 8
// speedup vs baseline: 1.2193x; 1.2193x over previous
#include <cuda_runtime.h>
#include <math.h>

#define Nn   8000
#define NPc  1000
#define Bc   8
#define Fc   1000
#define HCc  32
#define TRIc 499500
#define HIDc 128
#define EPSc 1e-5f
#define HPLANE (Bc * NPc * HCc)

// ---------------- persistent scratch ----------------
__device__ int    g_bar[32];
__device__ float  g_hbuf[2 * HPLANE];           // double-buffered h (layers 0,1)
__device__ float  g_emb[Bc * 96];
__device__ float  g_y1[Bc * HIDc];

// monotonic 2-block barrier (replay-safe, never reset)
__device__ __forceinline__ void gbar2(int slot) {
    __syncthreads();
    if (threadIdx.x == 0) {
        __threadfence();
        int r = atomicAdd(&g_bar[slot], 1);
        int target = (r / 2 + 1) * 2;
        while (atomicAdd(&g_bar[slot], 0) < target) { }
    }
    __syncthreads();
}

// ---------------- cheb helpers ----------------
// all-smem gather: weights + u16 indices + state in shared memory
__device__ __forceinline__ float gat16(const float* __restrict__ S,
                                       const float* __restrict__ sEw,
                                       const unsigned short* __restrict__ sEi,
                                       const int* __restrict__ sRow,
                                       int d, int ch) {
    int i0 = sRow[d], i1 = sRow[d + 1];
    float s = 0.f;
#pragma unroll 4
    for (int i = i0; i < i1; i++) {
        s = fmaf(sEw[i], S[((int)sEi[i] << 4) + ch], s);
    }
    return s;
}

// v = dot(h_prev[d][0:32], W_k[:, ch0+ch]) via half-warp shuffles
__device__ __forceinline__ float vdot(const float* __restrict__ hrow,
                                      const float* __restrict__ sWk, int ch) {
    float hlo = __ldcg(hrow + ch);
    float hhi = __ldcg(hrow + 16 + ch);
    float v = 0.f;
#pragma unroll
    for (int j = 0; j < 16; j++) {
        v = fmaf(__shfl_sync(0xFFFFFFFFu, hlo, j, 16), sWk[j * 16 + ch], v);
        v = fmaf(__shfl_sync(0xFFFFFFFFu, hhi, j, 16), sWk[(j + 16) * 16 + ch], v);
    }
    return v;
}

// ---------------- one ChebConv layer, fully in-block ----------------
__device__ void run_layer(int L, int b, int ch0, int ch, int t,
                          float* sA, float* sB, const float* sW,
                          const int* sRow, const float* sEw, const unsigned short* sEi,
                          const float* __restrict__ cw0,
                          const float* __restrict__ cbL)
{
    const float* hprev = g_hbuf + (L - 1) * HPLANE + b * NPc * HCc;

    // init: A := v4
    for (int d = t >> 4; d < NPc; d += 64) {
        float v = (L == 0) ? __ldg(cw0 + 4 * Fc * HCc + d * HCc + ch0 + ch)
                           : vdot(hprev + d * HCc, sW + 4 * 512, ch);
        sA[(d << 4) + ch] = v;
    }
    __syncthreads();
    // k=3: B := v3 + 2 G(A)
    for (int d = t >> 4; d < NPc; d += 64) {
        float v = (L == 0) ? __ldg(cw0 + 3 * Fc * HCc + d * HCc + ch0 + ch)
                           : vdot(hprev + d * HCc, sW + 3 * 512, ch);
        sB[(d << 4) + ch] = fmaf(2.f, gat16(sA, sEw, sEi, sRow, d, ch), v);
    }
    __syncthreads();
    // k=2: A := v2 + 2 G(B) - A
    for (int d = t >> 4; d < NPc; d += 64) {
        float v = (L == 0) ? __ldg(cw0 + 2 * Fc * HCc + d * HCc + ch0 + ch)
                           : vdot(hprev + d * HCc, sW + 2 * 512, ch);
        sA[(d << 4) + ch] = fmaf(2.f, gat16(sB, sEw, sEi, sRow, d, ch), v) - sA[(d << 4) + ch];
    }
    __syncthreads();
    // k=1: B := v1 + 2 G(A) - B
    for (int d = t >> 4; d < NPc; d += 64) {
        float v = (L == 0) ? __ldg(cw0 + 1 * Fc * HCc + d * HCc + ch0 + ch)
                           : vdot(hprev + d * HCc, sW + 1 * 512, ch);
        sB[(d << 4) + ch] = fmaf(2.f, gat16(sA, sEw, sEi, sRow, d, ch), v) - sB[(d << 4) + ch];
    }
    __syncthreads();
    // final: h = tanh(v0 + G(B) - A + bias); pool; store h
    float bl = __ldg(cbL + ch0 + ch);
    float pool = 0.f;
    for (int d = t >> 4; d < NPc; d += 64) {
        float v = (L == 0) ? __ldg(cw0 + 0 * Fc * HCc + d * HCc + ch0 + ch)
                           : vdot(hprev + d * HCc, sW + 0 * 512, ch);
        float h = tanhf(v + gat16(sB, sEw, sEi, sRow, d, ch) - sA[(d << 4) + ch] + bl);
        pool += h;
        if (L < 2) g_hbuf[L * HPLANE + b * NPc * HCc + d * HCc + ch0 + ch] = h;
    }
    atomicAdd(&g_emb[b * 96 + L * 32 + ch0 + ch], pool);
    __syncthreads();
}

// ---------------- the cheb kernel: 16 blocks, whole GNN ----------------
// smem floats: sA[16000] sB[16000] sW[2560] sEw[10000] sEi[5000(u16x10000)]
//              scan[1024] deg[1000] cnt[1000] row[1001] cur[1000]
#define SM_A    0
#define SM_B    16000
#define SM_W    32000
#define SM_EW   34560
#define SM_EI   44560
#define SM_SCAN 49560
#define SM_DEG  50584
#define SM_CNT  51584
#define SM_ROW  52584
#define SM_CUR  53585
#define SM_TOT  54585   // 218340 bytes

__global__ void __launch_bounds__(1024, 1)
cheb_kernel(const int* __restrict__ src, const int* __restrict__ dst, int E,
            const float* __restrict__ cw0, const float* __restrict__ cb0,
            const float* __restrict__ cw1, const float* __restrict__ cb1,
            const float* __restrict__ cw2, const float* __restrict__ cb2)
{
    extern __shared__ float sm[];
    float* sA = sm + SM_A;
    float* sB = sm + SM_B;
    float* sW = sm + SM_W;
    float* sEw = sm + SM_EW;
    unsigned short* sEi = (unsigned short*)(sm + SM_EI);
    int* sScan = (int*)(sm + SM_SCAN);
    int* sDeg  = (int*)(sm + SM_DEG);   // src (out) degree -> weights
    int* sCnt  = (int*)(sm + SM_CNT);   // dst (in) counts -> rowptr
    int* sRow  = (int*)(sm + SM_ROW);
    int* sCur  = (int*)(sm + SM_CUR);

    const int t = threadIdx.x, blk = blockIdx.x;
    const int b = blk >> 1, r = blk & 1;
    const int ch = t & 15, ch0 = r * 16;
    const int EB = E / Bc;              // 10000 for this problem
    const int e0 = b * EB;

    if (t < 48) {
        int L = t / 16, cc = t % 16;
        g_emb[b * 96 + L * 32 + ch0 + cc] = 0.f;
    }

    // ---- in-block CSR build (all in smem) ----
    for (int i = t; i < NPc; i += 1024) { sDeg[i] = 0; sCnt[i] = 0; }
    __syncthreads();
    for (int e = e0 + t; e < e0 + EB; e += 1024) {
        atomicAdd(&sDeg[__ldg(src + e) - b * NPc], 1);
        atomicAdd(&sCnt[__ldg(dst + e) - b * NPc], 1);
    }
    __syncthreads();
    {   // exclusive scan of sCnt -> sRow/sCur
        int c = (t < NPc) ? sCnt[t] : 0;
        sScan[t] = c;
        __syncthreads();
        for (int off = 1; off < 1024; off <<= 1) {
            int v = (t >= off) ? sScan[t - off] : 0;
            __syncthreads();
            sScan[t] += v;
            __syncthreads();
        }
        if (t < NPc) { sRow[t] = sScan[t] - c; sCur[t] = sScan[t] - c; }
        if (t == 0) sRow[NPc] = sScan[1023];
    }
    __syncthreads();
    for (int e = e0 + t; e < e0 + EB; e += 1024) {
        int s_ = __ldg(src + e) - b * NPc;
        int d_ = __ldg(dst + e) - b * NPc;
        int ds = sDeg[s_], dd = sDeg[d_];
        float w = (ds > 0 && dd > 0) ? -rsqrtf((float)ds) * rsqrtf((float)dd) : 0.f;
        int pos = atomicAdd(&sCur[d_], 1);
        sEw[pos] = w;
        sEi[pos] = (unsigned short)s_;
    }
    __syncthreads();

    // ---- layer 0 ----
    run_layer(0, b, ch0, ch, t, sA, sB, sW, sRow, sEw, sEi, cw0, cb0);

    __threadfence();
    gbar2(b * 2 + 0);
    for (int idx = t; idx < 5 * 512; idx += 1024) {
        int cc = idx & 15, j = (idx >> 4) & 31, k = idx >> 9;
        sW[idx] = __ldg(cw1 + k * 1024 + j * 32 + ch0 + cc);
    }
    __syncthreads();
    run_layer(1, b, ch0, ch, t, sA, sB, sW, sRow, sEw, sEi, nullptr, cb1);

    __threadfence();
    gbar2(b * 2 + 1);
    for (int idx = t; idx < 5 * 512; idx += 1024) {
        int cc = idx & 15, j = (idx >> 4) & 31, k = idx >> 9;
        sW[idx] = __ldg(cw2 + k * 1024 + j * 32 + ch0 + cc);
    }
    __syncthreads();
    run_layer(2, b, ch0, ch, t, sA, sB, sW, sRow, sEw, sEi, nullptr, cb2);
}

// ---------------- GEMM kernel: fused triu+fbn + W1 stream ----------------
#define GNB   444
#define GCH   256
#define GNCH  ((TRIc + GCH - 1) / GCH)   // 1952

__global__ void __launch_bounds__(256, 3)
gemm_kernel(const float* __restrict__ x, const float* __restrict__ W1,
            const float* __restrict__ bng, const float* __restrict__ bnb)
{
    __shared__ float sfb[GCH * 8];
    __shared__ float sred[4096];
    int t = threadIdx.x, wp = t >> 5, l = t & 31;
    float acc[Bc][4];
#pragma unroll
    for (int b = 0; b < Bc; b++)
#pragma unroll
        for (int q = 0; q < 4; q++) acc[b][q] = 0.f;

    for (int c = blockIdx.x; c < GNCH; c += GNB) {
        int fbase = c * GCH;
        __syncthreads();
        // phase A: fbn for 256 rows (1 per thread)
        {
            int f = fbase + t;
            float res[Bc];
            if (f < TRIc) {
                float disc = 3996001.0f - 8.0f * (float)f;
                float sq = sqrtf(fmaxf(disc, 0.f));
                int i = (int)((1999.0f - sq) * 0.5f);
                i = max(0, min(i, Fc - 2));
                while (i + 1 <= Fc - 2 && (((long long)(i + 1) * (1999 - (i + 1))) >> 1) <= (long long)f) i++;
                while (i > 0 && (((long long)i * (1999 - i)) >> 1) > (long long)f) i--;
                int Si = (int)(((long long)i * (1999 - i)) >> 1);
                int j = i + 1 + (f - Si);
                float v[Bc]; float m = 0.f;
#pragma unroll
                for (int b = 0; b < Bc; b++) {
                    v[b] = __ldg(x + ((size_t)(b * Fc + i) * Fc + j));
                    m += v[b];
                }
                m *= 0.125f;
                float var = 0.f;
#pragma unroll
                for (int b = 0; b < Bc; b++) { float dd = v[b] - m; var = fmaf(dd, dd, var); }
                var *= 0.125f;
                float sc = rsqrtf(var + EPSc) * __ldg(bng + f);
                float sh = __ldg(bnb + f);
#pragma unroll
                for (int b = 0; b < Bc; b++) res[b] = (v[b] - m) * sc + sh;
            } else {
#pragma unroll
                for (int b = 0; b < Bc; b++) res[b] = 0.f;
            }
            *(float4*)&sfb[t * 8]     = make_float4(res[0], res[1], res[2], res[3]);
            *(float4*)&sfb[t * 8 + 4] = make_float4(res[4], res[5], res[6], res[7]);
        }
        __syncthreads();
        // phase B: warp wp streams rows [wp*32, wp*32+32), batch-4 prefetch
        int r0 = wp * 32;
#pragma unroll 2
        for (int rb = 0; rb < 32; rb += 4) {
            float4 w[4];
#pragma unroll
            for (int u = 0; u < 4; u++) {
                int f2 = min(fbase + r0 + rb + u, TRIc - 1);
                w[u] = __ldcs((const float4*)(W1 + (size_t)f2 * HIDc + l * 4));
            }
#pragma unroll
            for (int u = 0; u < 4; u++) {
                int fl = r0 + rb + u;
                float4 f0 = *(const float4*)&sfb[fl * 8];
                float4 f1 = *(const float4*)&sfb[fl * 8 + 4];
                acc[0][0] = fmaf(f0.x, w[u].x, acc[0][0]); acc[0][1] = fmaf(f0.x, w[u].y, acc[0][1]);
                acc[0][2] = fmaf(f0.x, w[u].z, acc[0][2]); acc[0][3] = fmaf(f0.x, w[u].w, acc[0][3]);
                acc[1][0] = fmaf(f0.y, w[u].x, acc[1][0]); acc[1][1] = fmaf(f0.y, w[u].y, acc[1][1]);
                acc[1][2] = fmaf(f0.y, w[u].z, acc[1][2]); acc[1][3] = fmaf(f0.y, w[u].w, acc[1][3]);
                acc[2][0] = fmaf(f0.z, w[u].x, acc[2][0]); acc[2][1] = fmaf(f0.z, w[u].y, acc[2][1]);
                acc[2][2] = fmaf(f0.z, w[u].z, acc[2][2]); acc[2][3] = fmaf(f0.z, w[u].w, acc[2][3]);
                acc[3][0] = fmaf(f0.w, w[u].x, acc[3][0]); acc[3][1] = fmaf(f0.w, w[u].y, acc[3][1]);
                acc[3][2] = fmaf(f0.w, w[u].z, acc[3][2]); acc[3][3] = fmaf(f0.w, w[u].w, acc[3][3]);
                acc[4][0] = fmaf(f1.x, w[u].x, acc[4][0]); acc[4][1] = fmaf(f1.x, w[u].y, acc[4][1]);
                acc[4][2] = fmaf(f1.x, w[u].z, acc[4][2]); acc[4][3] = fmaf(f1.x, w[u].w, acc[4][3]);
                acc[5][0] = fmaf(f1.y, w[u].x, acc[5][0]); acc[5][1] = fmaf(f1.y, w[u].y, acc[5][1]);
                acc[5][2] = fmaf(f1.y, w[u].z, acc[5][2]); acc[5][3] = fmaf(f1.y, w[u].w, acc[5][3]);
                acc[6][0] = fmaf(f1.z, w[u].x, acc[6][0]); acc[6][1] = fmaf(f1.z, w[u].y, acc[6][1]);
                acc[6][2] = fmaf(f1.z, w[u].z, acc[6][2]); acc[6][3] = fmaf(f1.z, w[u].w, acc[6][3]);
                acc[7][0] = fmaf(f1.w, w[u].x, acc[7][0]); acc[7][1] = fmaf(f1.w, w[u].y, acc[7][1]);
                acc[7][2] = fmaf(f1.w, w[u].z, acc[7][2]); acc[7][3] = fmaf(f1.w, w[u].w, acc[7][3]);
            }
        }
    }
    __syncthreads();
    // tree reduce 8 warps -> 1
    for (int half = 4; half >= 1; half >>= 1) {
        if (wp >= half && wp < 2 * half) {
            float* reg = sred + (wp - half) * 1024;
#pragma unroll
            for (int b = 0; b < Bc; b++)
                *(float4*)&reg[b * HIDc + l * 4] =
                    make_float4(acc[b][0], acc[b][1], acc[b][2], acc[b][3]);
        }
        __syncthreads();
        if (wp < half) {
            float* reg = sred + wp * 1024;
#pragma unroll
            for (int b = 0; b < Bc; b++) {
                float4 z = *(const float4*)&reg[b * HIDc + l * 4];
                acc[b][0] += z.x; acc[b][1] += z.y; acc[b][2] += z.z; acc[b][3] += z.w;
            }
        }
        __syncthreads();
    }
    if (wp == 0) {
#pragma unroll
        for (int b = 0; b < Bc; b++)
#pragma unroll
            for (int q = 0; q < 4; q++)
                atomicAdd(&g_y1[b * HIDc + l * 4 + q], acc[b][q]);
    }
}

// ---------------- head: hbn output + MLP + log-softmax ----------------
__global__ void head_kernel(const float* __restrict__ bnhg, const float* __restrict__ bnhb,
                            const float* __restrict__ b1,
                            const float* __restrict__ g1, const float* __restrict__ be1,
                            const float* __restrict__ W2, const float* __restrict__ b2,
                            const float* __restrict__ g2, const float* __restrict__ be2,
                            const float* __restrict__ W3, const float* __restrict__ b3,
                            const float* __restrict__ g3, const float* __restrict__ be3,
                            const float* __restrict__ W4, const float* __restrict__ b4,
                            float* __restrict__ out) {
    __shared__ float a1[8 * 128];
    __shared__ float a2[8 * 64];
    __shared__ float a3[8 * 64];
    __shared__ float lg[16];
    int t = threadIdx.x;

    if (t < 96) {
        float e[Bc]; float m = 0.f;
#pragma unroll
        for (int b = 0; b < Bc; b++) { e[b] = __ldcg(&g_emb[b * 96 + t]) * (1.f / (float)NPc); m += e[b]; }
        m *= 0.125f;
        float v = 0.f;
#pragma unroll
        for (int b = 0; b < Bc; b++) { float dd = e[b] - m; v = fmaf(dd, dd, v); }
        v *= 0.125f;
        float sc = rsqrtf(v + EPSc) * __ldg(bnhg + t);
        float sh = __ldg(bnhb + t);
#pragma unroll
        for (int b = 0; b < Bc; b++) out[16 + b * 96 + t] = (e[b] - m) * sc + sh;
    }

    for (int idx = t; idx < 1024; idx += 256) a1[idx] = __ldcg(&g_y1[idx]) + __ldg(&b1[idx & 127]);
    __syncthreads();
    if (t < 128) {
        float m = 0.f;
#pragma unroll
        for (int b = 0; b < Bc; b++) m += a1[b * 128 + t];
        m *= 0.125f;
        float v = 0.f;
#pragma unroll
        for (int b = 0; b < Bc; b++) { float dd = a1[b * 128 + t] - m; v = fmaf(dd, dd, v); }
        v *= 0.125f;
        float sc = rsqrtf(v + EPSc) * __ldg(g1 + t);
        float sh = __ldg(be1 + t);
#pragma unroll
        for (int b = 0; b < Bc; b++) {
            float z = (a1[b * 128 + t] - m) * sc + sh;
            a1[b * 128 + t] = z > 0.f ? z : 0.f;
        }
    }
    __syncthreads();
    for (int idx = t; idx < 512; idx += 256) {
        int b = idx >> 6, h = idx & 63;
        float s = __ldg(b2 + h);
        for (int j = 0; j < 128; j++) s = fmaf(a1[b * 128 + j], __ldg(W2 + j * 64 + h), s);
        a2[idx] = s;
    }
    __syncthreads();
    if (t < 64) {
        float m = 0.f;
#pragma unroll
        for (int b = 0; b < Bc; b++) m += a2[b * 64 + t];
        m *= 0.125f;
        float v = 0.f;
#pragma unroll
        for (int b = 0; b < Bc; b++) { float dd = a2[b * 64 + t] - m; v = fmaf(dd, dd, v); }
        v *= 0.125f;
        float sc = rsqrtf(v + EPSc) * __ldg(g2 + t);
        float sh = __ldg(be2 + t);
#pragma unroll
        for (int b = 0; b < Bc; b++) {
            float z = (a2[b * 64 + t] - m) * sc + sh;
            a2[b * 64 + t] = z > 0.f ? z : 0.f;
        }
    }
    __syncthreads();
    for (int idx = t; idx < 512; idx += 256) {
        int b = idx >> 6, h = idx & 63;
        float s = __ldg(b3 + h);
        for (int j = 0; j < 64; j++) s = fmaf(a2[b * 64 + j], __ldg(W3 + j * 64 + h), s);
        a3[idx] = s;
    }
    __syncthreads();
    if (t < 64) {
        float m = 0.f;
#pragma unroll
        for (int b = 0; b < Bc; b++) m += a3[b * 64 + t];
        m *= 0.125f;
        float v = 0.f;
#pragma unroll
        for (int b = 0; b < Bc; b++) { float dd = a3[b * 64 + t] - m; v = fmaf(dd, dd, v); }
        v *= 0.125f;
        float sc = rsqrtf(v + EPSc) * __ldg(g3 + t);
        float sh = __ldg(be3 + t);
#pragma unroll
        for (int b = 0; b < Bc; b++) {
            float z = (a3[b * 64 + t] - m) * sc + sh;
            a3[b * 64 + t] = z > 0.f ? z : 0.f;
        }
    }
    __syncthreads();
    if (t < 16) {
        int b = t >> 1, c = t & 1;
        float s = __ldg(b4 + c);
        for (int j = 0; j < 64; j++) s = fmaf(a3[b * 64 + j], __ldg(W4 + j * 2 + c), s);
        lg[t] = s;
    }
    __syncthreads();
    if (t < 8) {
        float l0 = lg[t * 2], l1 = lg[t * 2 + 1];
        float m = fmaxf(l0, l1);
        float lse = m + logf(expf(l0 - m) + expf(l1 - m));
        out[t * 2 + 0] = l0 - lse;
        out[t * 2 + 1] = l1 - lse;
    }
}

// ---------------- host driver ----------------
extern "C" void kernel_launch(void* const* d_in, const int* in_sizes, int n_in,
                              void* d_out, int out_size) {
    const float* x    = (const float*)d_in[0];
    const int*   ei   = (const int*)d_in[1];
    int E = in_sizes[1] / 2;
    const int* src = ei;
    const int* dst = ei + E;
    const float* cw0  = (const float*)d_in[3];
    const float* cb0  = (const float*)d_in[4];
    const float* cw1  = (const float*)d_in[5];
    const float* cb1  = (const float*)d_in[6];
    const float* cw2  = (const float*)d_in[7];
    const float* cb2  = (const float*)d_in[8];
    const float* bnhg = (const float*)d_in[9];
    const float* bnhb = (const float*)d_in[10];
    const float* bng  = (const float*)d_in[11];
    const float* bnb  = (const float*)d_in[12];
    const float* w1   = (const float*)d_in[13];
    const float* b1   = (const float*)d_in[14];
    const float* g1   = (const float*)d_in[15];
    const float* be1  = (const float*)d_in[16];
    const float* W2   = (const float*)d_in[17];
    const float* b2   = (const float*)d_in[18];
    const float* g2   = (const float*)d_in[19];
    const float* be2  = (const float*)d_in[20];
    const float* W3   = (const float*)d_in[21];
    const float* b3   = (const float*)d_in[22];
    const float* g3   = (const float*)d_in[23];
    const float* be3  = (const float*)d_in[24];
    const float* W4   = (const float*)d_in[25];
    const float* b4   = (const float*)d_in[26];
    float* out = (float*)d_out;

    void* y1ptr = nullptr;
    cudaGetSymbolAddress(&y1ptr, g_y1);

    // fork the GEMM branch onto a second stream
    cudaStream_t s2 = 0;
    cudaEvent_t evF = 0, evJ = 0;
    bool forked = (cudaStreamCreateWithFlags(&s2, cudaStreamNonBlocking) == cudaSuccess) &&
                  (cudaEventCreateWithFlags(&evF, cudaEventDisableTiming) == cudaSuccess) &&
                  (cudaEventCreateWithFlags(&evJ, cudaEventDisableTiming) == cudaSuccess);
    if (!forked) s2 = 0;

    if (forked) {
        cudaEventRecord(evF, 0);
        cudaStreamWaitEvent(s2, evF, 0);
    }
    cudaMemsetAsync(y1ptr, 0, Bc * HIDc * sizeof(float), s2);
    gemm_kernel<<<GNB, 256, 0, s2>>>(x, w1, bng, bnb);
    if (forked) cudaEventRecord(evJ, s2);

    // cheb branch (stream 0)
    cudaFuncSetAttribute(cheb_kernel, cudaFuncAttributeMaxDynamicSharedMemorySize,
                         SM_TOT * (int)sizeof(float));
    cheb_kernel<<<16, 1024, SM_TOT * sizeof(float)>>>(src, dst, E,
                                                      cw0, cb0, cw1, cb1, cw2, cb2);

    if (forked) cudaStreamWaitEvent(0, evJ, 0);
    head_kernel<<<1, 256>>>(bnhg, bnhb, b1, g1, be1, W2, b2, g2, be2,
                            W3, b3, g3, be3, W4, b4, out);
}

// round 9
// speedup vs baseline: 1.4387x; 1.1799x over previous
#include <cuda_runtime.h>
#include <math.h>

#define Nn   8000
#define NPc  1000
#define Bc   8
#define Fc   1000
#define HCc  32
#define TRIc 499500
#define HIDc 128
#define EPSc 1e-5f
#define HPLANE (Bc * NPc * HCc)

// ---------------- persistent scratch ----------------
__device__ int    g_bar[32];
__device__ float  g_hbuf[2 * HPLANE];            // h planes (layers 0,1)
__device__ float  g_hv[16 * 5 * 16000];          // per-block v-tables: [blk][k][d][ch16]
__device__ float  g_emb[Bc * 96];
__device__ float  g_y1[Bc * HIDc];

// monotonic 2-block barrier (replay-safe, never reset)
__device__ __forceinline__ void gbar2(int slot) {
    __syncthreads();
    if (threadIdx.x == 0) {
        __threadfence();
        int r = atomicAdd(&g_bar[slot], 1);
        int target = (r / 2 + 1) * 2;
        while (atomicAdd(&g_bar[slot], 0) < target) { }
    }
    __syncthreads();
}

// ---------------- cheb helpers ----------------
__device__ __forceinline__ float gat16(const float* __restrict__ S,
                                       const float* __restrict__ sEw,
                                       const unsigned short* __restrict__ sEi,
                                       const int* __restrict__ sRow,
                                       int d, int ch) {
    int i0 = sRow[d], i1 = sRow[d + 1];
    float s = 0.f;
#pragma unroll 4
    for (int i = i0; i < i1; i++) {
        s = fmaf(sEw[i], S[((int)sEi[i] << 4) + ch], s);
    }
    return s;
}

// ---------------- v-table pass: vplanes[k][d][ch] = dot(h[d][:], W[k][:][ch0+ch]) ----------------
// warp-specialized: warps 0..29, kg = w/6 handles table k=kg; weights register-cached.
__device__ void vpass(const float* __restrict__ hprev,   // batch base, [d][32]
                      const float* __restrict__ cwL,     // (5,32,32)
                      float* __restrict__ vplanes,       // block base, 5*16000
                      int ch0, int t)
{
    int w = t >> 5, l = t & 31;
    int ch = l & 15;
    if (w < 30) {
        int kg = w / 6, wi = w % 6;
        float wreg[32];
#pragma unroll
        for (int j = 0; j < 32; j++)
            wreg[j] = __ldg(cwL + kg * 1024 + j * 32 + ch0 + ch);
        float* vp = vplanes + kg * 16000;
        for (int d = wi * 2 + (l >> 4); d < NPc; d += 12) {
            float hlo = __ldcg(hprev + d * 32 + ch);
            float hhi = __ldcg(hprev + d * 32 + 16 + ch);
            float a = 0.f;
#pragma unroll
            for (int j = 0; j < 16; j++)
                a = fmaf(__shfl_sync(0xFFFFFFFFu, hlo, j, 16), wreg[j], a);
#pragma unroll
            for (int j = 0; j < 16; j++)
                a = fmaf(__shfl_sync(0xFFFFFFFFu, hhi, j, 16), wreg[j + 16], a);
            vp[(d << 4) + ch] = a;
        }
    }
    __syncthreads();
}

// ---------------- one ChebConv layer (v from precomputed tables) ----------------
// mode 0: v_k[d][c] = cw0[k][d][ch0+c] (layer-0 identity input)
// mode 1: v_k[d][c] = vtab[k*16000 + d*16 + c]
__device__ void run_layer(int L, int mode, int b, int ch0, int ch, int t,
                          float* sA, float* sB,
                          const int* sRow, const float* sEw, const unsigned short* sEi,
                          const float* __restrict__ vsrc,   // cw0 (mode0) or vtab (mode1)
                          const float* __restrict__ cbL)
{
#define VREAD(k, d) (mode == 0 ? __ldg(vsrc + (k) * 32000 + (d) * 32 + ch0 + ch) \
                               : __ldcg(vsrc + (k) * 16000 + ((d) << 4) + ch))
    // init: A := v4
    for (int d = t >> 4; d < NPc; d += 64)
        sA[(d << 4) + ch] = VREAD(4, d);
    __syncthreads();
    // k=3: B := v3 + 2 G(A)
    for (int d = t >> 4; d < NPc; d += 64)
        sB[(d << 4) + ch] = fmaf(2.f, gat16(sA, sEw, sEi, sRow, d, ch), VREAD(3, d));
    __syncthreads();
    // k=2: A := v2 + 2 G(B) - A
    for (int d = t >> 4; d < NPc; d += 64)
        sA[(d << 4) + ch] = fmaf(2.f, gat16(sB, sEw, sEi, sRow, d, ch), VREAD(2, d)) - sA[(d << 4) + ch];
    __syncthreads();
    // k=1: B := v1 + 2 G(A) - B
    for (int d = t >> 4; d < NPc; d += 64)
        sB[(d << 4) + ch] = fmaf(2.f, gat16(sA, sEw, sEi, sRow, d, ch), VREAD(1, d)) - sB[(d << 4) + ch];
    __syncthreads();
    // final: h = tanh(v0 + G(B) - A + bias); pool; store h
    float bl = __ldg(cbL + ch0 + ch);
    float pool = 0.f;
    for (int d = t >> 4; d < NPc; d += 64) {
        float h = tanhf(VREAD(0, d) + gat16(sB, sEw, sEi, sRow, d, ch)
                        - sA[(d << 4) + ch] + bl);
        pool += h;
        if (L < 2) g_hbuf[L * HPLANE + b * NPc * HCc + d * HCc + ch0 + ch] = h;
    }
    atomicAdd(&g_emb[b * 96 + L * 32 + ch0 + ch], pool);
    __syncthreads();
#undef VREAD
}

// ---------------- the cheb kernel: 16 blocks ----------------
// smem floats: sA[16000] sB[16000] sEw[10000] sEi(u16 x 10000 = 5000 floats)
//              scan[1024] deg[1000] cnt[1000] row[1001] cur[1000]
#define SM_A    0
#define SM_B    16000
#define SM_EW   32000
#define SM_EI   42000
#define SM_SCAN 47000
#define SM_DEG  48024
#define SM_CNT  49024
#define SM_ROW  50024
#define SM_CUR  51025
#define SM_TOT  52025   // 208100 bytes

__global__ void __launch_bounds__(1024, 1)
cheb_kernel(const int* __restrict__ src, const int* __restrict__ dst, int E,
            const float* __restrict__ cw0, const float* __restrict__ cb0,
            const float* __restrict__ cw1, const float* __restrict__ cb1,
            const float* __restrict__ cw2, const float* __restrict__ cb2)
{
    extern __shared__ float sm[];
    float* sA  = sm + SM_A;
    float* sB  = sm + SM_B;
    float* sEw = sm + SM_EW;
    unsigned short* sEi = (unsigned short*)(sm + SM_EI);
    int* sScan = (int*)(sm + SM_SCAN);
    int* sDeg  = (int*)(sm + SM_DEG);
    int* sCnt  = (int*)(sm + SM_CNT);
    int* sRow  = (int*)(sm + SM_ROW);
    int* sCur  = (int*)(sm + SM_CUR);

    const int t = threadIdx.x, blk = blockIdx.x;
    const int b = blk >> 1, r = blk & 1;
    const int ch = t & 15, ch0 = r * 16;
    const int EB = E / Bc;
    const int e0 = b * EB;
    float* vtab = g_hv + blk * 5 * 16000;

    if (t < 48) {
        int L = t / 16, cc = t % 16;
        g_emb[b * 96 + L * 32 + ch0 + cc] = 0.f;
    }

    // ---- in-block CSR build ----
    for (int i = t; i < NPc; i += 1024) { sDeg[i] = 0; sCnt[i] = 0; }
    __syncthreads();
    for (int e = e0 + t; e < e0 + EB; e += 1024) {
        atomicAdd(&sDeg[__ldg(src + e) - b * NPc], 1);
        atomicAdd(&sCnt[__ldg(dst + e) - b * NPc], 1);
    }
    __syncthreads();
    {
        int c = (t < NPc) ? sCnt[t] : 0;
        sScan[t] = c;
        __syncthreads();
        for (int off = 1; off < 1024; off <<= 1) {
            int v = (t >= off) ? sScan[t - off] : 0;
            __syncthreads();
            sScan[t] += v;
            __syncthreads();
        }
        if (t < NPc) { sRow[t] = sScan[t] - c; sCur[t] = sScan[t] - c; }
        if (t == 0) sRow[NPc] = sScan[1023];
    }
    __syncthreads();
    for (int e = e0 + t; e < e0 + EB; e += 1024) {
        int s_ = __ldg(src + e) - b * NPc;
        int d_ = __ldg(dst + e) - b * NPc;
        int ds = sDeg[s_], dd = sDeg[d_];
        float w = (ds > 0 && dd > 0) ? -rsqrtf((float)ds) * rsqrtf((float)dd) : 0.f;
        int pos = atomicAdd(&sCur[d_], 1);
        sEw[pos] = w;
        sEi[pos] = (unsigned short)s_;
    }
    __syncthreads();

    // ---- layer 0 (v-tables = cw0 planes) ----
    run_layer(0, 0, b, ch0, ch, t, sA, sB, sRow, sEw, sEi, cw0, cb0);

    __threadfence();
    gbar2(b * 2 + 0);
    vpass(g_hbuf + 0 * HPLANE + b * NPc * HCc, cw1, vtab, ch0, t);
    run_layer(1, 1, b, ch0, ch, t, sA, sB, sRow, sEw, sEi, vtab, cb1);

    __threadfence();
    gbar2(b * 2 + 1);
    vpass(g_hbuf + 1 * HPLANE + b * NPc * HCc, cw2, vtab, ch0, t);
    run_layer(2, 1, b, ch0, ch, t, sA, sB, sRow, sEw, sEi, vtab, cb2);
}

// ---------------- GEMM kernel: fused triu+fbn + W1 stream (double-buffered) ----------------
#define GNB   396
#define GCH   256
#define GNCH  ((TRIc + GCH - 1) / GCH)   // 1952

__device__ __forceinline__ void triidx(int f, int& i, int& j) {
    float disc = 3996001.0f - 8.0f * (float)f;
    float sq = sqrtf(fmaxf(disc, 0.f));
    i = (int)((1999.0f - sq) * 0.5f);
    i = max(0, min(i, Fc - 2));
    while (i + 1 <= Fc - 2 && (((long long)(i + 1) * (1999 - (i + 1))) >> 1) <= (long long)f) i++;
    while (i > 0 && (((long long)i * (1999 - i)) >> 1) > (long long)f) i--;
    int Si = (int)(((long long)i * (1999 - i)) >> 1);
    j = i + 1 + (f - Si);
}

__global__ void __launch_bounds__(256, 3)
gemm_kernel(const float* __restrict__ x, const float* __restrict__ W1,
            const float* __restrict__ bng, const float* __restrict__ bnb)
{
    __shared__ float sfb[2][GCH * 8];
    __shared__ float sred[4096];
    int t = threadIdx.x, wp = t >> 5, l = t & 31;
    float acc[Bc][4];
#pragma unroll
    for (int b = 0; b < Bc; b++)
#pragma unroll
        for (int q = 0; q < 4; q++) acc[b][q] = 0.f;

    // prologue: fbn for first chunk
    {
        int f = blockIdx.x * GCH + t;
        float res[Bc];
        if (f < TRIc) {
            int i, j; triidx(f, i, j);
            float v[Bc]; float m = 0.f;
#pragma unroll
            for (int b = 0; b < Bc; b++) {
                v[b] = __ldg(x + ((size_t)(b * Fc + i) * Fc + j));
                m += v[b];
            }
            m *= 0.125f;
            float var = 0.f;
#pragma unroll
            for (int b = 0; b < Bc; b++) { float dd = v[b] - m; var = fmaf(dd, dd, var); }
            var *= 0.125f;
            float sc = rsqrtf(var + EPSc) * __ldg(bng + f);
            float sh = __ldg(bnb + f);
#pragma unroll
            for (int b = 0; b < Bc; b++) res[b] = (v[b] - m) * sc + sh;
        } else {
#pragma unroll
            for (int b = 0; b < Bc; b++) res[b] = 0.f;
        }
        *(float4*)&sfb[0][t * 8]     = make_float4(res[0], res[1], res[2], res[3]);
        *(float4*)&sfb[0][t * 8 + 4] = make_float4(res[4], res[5], res[6], res[7]);
    }
    __syncthreads();

    int p = 0;
    for (int c = blockIdx.x; c < GNCH; c += GNB) {
        int cn = c + GNB;
        bool hasNext = (cn < GNCH);
        // prefetch next chunk's x rows + bn params into registers (loads in flight
        // during the W1 stream below)
        float xv[Bc]; float bgv = 0.f, bbv = 0.f; bool val = false; int fN = 0;
        if (hasNext) {
            fN = cn * GCH + t;
            val = (fN < TRIc);
            if (val) {
                int i, j; triidx(fN, i, j);
#pragma unroll
                for (int b = 0; b < Bc; b++)
                    xv[b] = __ldg(x + ((size_t)(b * Fc + i) * Fc + j));
                bgv = __ldg(bng + fN);
                bbv = __ldg(bnb + fN);
            }
        }
        // stream W1 for chunk c
        {
            int fbase = c * GCH;
            int r0 = wp * 32;
            const float* buf = sfb[p];
#pragma unroll 2
            for (int rb = 0; rb < 32; rb += 4) {
                float4 w[4];
#pragma unroll
                for (int u = 0; u < 4; u++) {
                    int f2 = min(fbase + r0 + rb + u, TRIc - 1);
                    w[u] = __ldcs((const float4*)(W1 + (size_t)f2 * HIDc + l * 4));
                }
#pragma unroll
                for (int u = 0; u < 4; u++) {
                    int fl = r0 + rb + u;
                    float4 f0 = *(const float4*)&buf[fl * 8];
                    float4 f1 = *(const float4*)&buf[fl * 8 + 4];
                    acc[0][0] = fmaf(f0.x, w[u].x, acc[0][0]); acc[0][1] = fmaf(f0.x, w[u].y, acc[0][1]);
                    acc[0][2] = fmaf(f0.x, w[u].z, acc[0][2]); acc[0][3] = fmaf(f0.x, w[u].w, acc[0][3]);
                    acc[1][0] = fmaf(f0.y, w[u].x, acc[1][0]); acc[1][1] = fmaf(f0.y, w[u].y, acc[1][1]);
                    acc[1][2] = fmaf(f0.y, w[u].z, acc[1][2]); acc[1][3] = fmaf(f0.y, w[u].w, acc[1][3]);
                    acc[2][0] = fmaf(f0.z, w[u].x, acc[2][0]); acc[2][1] = fmaf(f0.z, w[u].y, acc[2][1]);
                    acc[2][2] = fmaf(f0.z, w[u].z, acc[2][2]); acc[2][3] = fmaf(f0.z, w[u].w, acc[2][3]);
                    acc[3][0] = fmaf(f0.w, w[u].x, acc[3][0]); acc[3][1] = fmaf(f0.w, w[u].y, acc[3][1]);
                    acc[3][2] = fmaf(f0.w, w[u].z, acc[3][2]); acc[3][3] = fmaf(f0.w, w[u].w, acc[3][3]);
                    acc[4][0] = fmaf(f1.x, w[u].x, acc[4][0]); acc[4][1] = fmaf(f1.x, w[u].y, acc[4][1]);
                    acc[4][2] = fmaf(f1.x, w[u].z, acc[4][2]); acc[4][3] = fmaf(f1.x, w[u].w, acc[4][3]);
                    acc[5][0] = fmaf(f1.y, w[u].x, acc[5][0]); acc[5][1] = fmaf(f1.y, w[u].y, acc[5][1]);
                    acc[5][2] = fmaf(f1.y, w[u].z, acc[5][2]); acc[5][3] = fmaf(f1.y, w[u].w, acc[5][3]);
                    acc[6][0] = fmaf(f1.z, w[u].x, acc[6][0]); acc[6][1] = fmaf(f1.z, w[u].y, acc[6][1]);
                    acc[6][2] = fmaf(f1.z, w[u].z, acc[6][2]); acc[6][3] = fmaf(f1.z, w[u].w, acc[6][3]);
                    acc[7][0] = fmaf(f1.w, w[u].x, acc[7][0]); acc[7][1] = fmaf(f1.w, w[u].y, acc[7][1]);
                    acc[7][2] = fmaf(f1.w, w[u].z, acc[7][2]); acc[7][3] = fmaf(f1.w, w[u].w, acc[7][3]);
                }
            }
        }
        // finish fbn for next chunk into the other buffer
        if (hasNext) {
            float res[Bc];
            if (val) {
                float m = 0.f;
#pragma unroll
                for (int b = 0; b < Bc; b++) m += xv[b];
                m *= 0.125f;
                float var = 0.f;
#pragma unroll
                for (int b = 0; b < Bc; b++) { float dd = xv[b] - m; var = fmaf(dd, dd, var); }
                var *= 0.125f;
                float sc = rsqrtf(var + EPSc) * bgv;
#pragma unroll
                for (int b = 0; b < Bc; b++) res[b] = (xv[b] - m) * sc + bbv;
            } else {
#pragma unroll
                for (int b = 0; b < Bc; b++) res[b] = 0.f;
            }
            *(float4*)&sfb[p ^ 1][t * 8]     = make_float4(res[0], res[1], res[2], res[3]);
            *(float4*)&sfb[p ^ 1][t * 8 + 4] = make_float4(res[4], res[5], res[6], res[7]);
        }
        __syncthreads();
        p ^= 1;
    }

    // tree reduce 8 warps -> 1
    for (int half = 4; half >= 1; half >>= 1) {
        if (wp >= half && wp < 2 * half) {
            float* reg = sred + (wp - half) * 1024;
#pragma unroll
            for (int b = 0; b < Bc; b++)
                *(float4*)&reg[b * HIDc + l * 4] =
                    make_float4(acc[b][0], acc[b][1], acc[b][2], acc[b][3]);
        }
        __syncthreads();
        if (wp < half) {
            float* reg = sred + wp * 1024;
#pragma unroll
            for (int b = 0; b < Bc; b++) {
                float4 z = *(const float4*)&reg[b * HIDc + l * 4];
                acc[b][0] += z.x; acc[b][1] += z.y; acc[b][2] += z.z; acc[b][3] += z.w;
            }
        }
        __syncthreads();
    }
    if (wp == 0) {
#pragma unroll
        for (int b = 0; b < Bc; b++)
#pragma unroll
            for (int q = 0; q < 4; q++)
                atomicAdd(&g_y1[b * HIDc + l * 4 + q], acc[b][q]);
    }
}

// ---------------- head: hbn output + MLP + log-softmax ----------------
__global__ void head_kernel(const float* __restrict__ bnhg, const float* __restrict__ bnhb,
                            const float* __restrict__ b1,
                            const float* __restrict__ g1, const float* __restrict__ be1,
                            const float* __restrict__ W2, const float* __restrict__ b2,
                            const float* __restrict__ g2, const float* __restrict__ be2,
                            const float* __restrict__ W3, const float* __restrict__ b3,
                            const float* __restrict__ g3, const float* __restrict__ be3,
                            const float* __restrict__ W4, const float* __restrict__ b4,
                            float* __restrict__ out) {
    __shared__ float a1[8 * 128];
    __shared__ float a2[8 * 64];
    __shared__ float a3[8 * 64];
    __shared__ float lg[16];
    int t = threadIdx.x;

    if (t < 96) {
        float e[Bc]; float m = 0.f;
#pragma unroll
        for (int b = 0; b < Bc; b++) { e[b] = __ldcg(&g_emb[b * 96 + t]) * (1.f / (float)NPc); m += e[b]; }
        m *= 0.125f;
        float v = 0.f;
#pragma unroll
        for (int b = 0; b < Bc; b++) { float dd = e[b] - m; v = fmaf(dd, dd, v); }
        v *= 0.125f;
        float sc = rsqrtf(v + EPSc) * __ldg(bnhg + t);
        float sh = __ldg(bnhb + t);
#pragma unroll
        for (int b = 0; b < Bc; b++) out[16 + b * 96 + t] = (e[b] - m) * sc + sh;
    }

    for (int idx = t; idx < 1024; idx += 256) a1[idx] = __ldcg(&g_y1[idx]) + __ldg(&b1[idx & 127]);
    __syncthreads();
    if (t < 128) {
        float m = 0.f;
#pragma unroll
        for (int b = 0; b < Bc; b++) m += a1[b * 128 + t];
        m *= 0.125f;
        float v = 0.f;
#pragma unroll
        for (int b = 0; b < Bc; b++) { float dd = a1[b * 128 + t] - m; v = fmaf(dd, dd, v); }
        v *= 0.125f;
        float sc = rsqrtf(v + EPSc) * __ldg(g1 + t);
        float sh = __ldg(be1 + t);
#pragma unroll
        for (int b = 0; b < Bc; b++) {
            float z = (a1[b * 128 + t] - m) * sc + sh;
            a1[b * 128 + t] = z > 0.f ? z : 0.f;
        }
    }
    __syncthreads();
    for (int idx = t; idx < 512; idx += 256) {
        int b = idx >> 6, h = idx & 63;
        float s = __ldg(b2 + h);
        for (int j = 0; j < 128; j++) s = fmaf(a1[b * 128 + j], __ldg(W2 + j * 64 + h), s);
        a2[idx] = s;
    }
    __syncthreads();
    if (t < 64) {
        float m = 0.f;
#pragma unroll
        for (int b = 0; b < Bc; b++) m += a2[b * 64 + t];
        m *= 0.125f;
        float v = 0.f;
#pragma unroll
        for (int b = 0; b < Bc; b++) { float dd = a2[b * 64 + t] - m; v = fmaf(dd, dd, v); }
        v *= 0.125f;
        float sc = rsqrtf(v + EPSc) * __ldg(g2 + t);
        float sh = __ldg(be2 + t);
#pragma unroll
        for (int b = 0; b < Bc; b++) {
            float z = (a2[b * 64 + t] - m) * sc + sh;
            a2[b * 64 + t] = z > 0.f ? z : 0.f;
        }
    }
    __syncthreads();
    for (int idx = t; idx < 512; idx += 256) {
        int b = idx >> 6, h = idx & 63;
        float s = __ldg(b3 + h);
        for (int j = 0; j < 64; j++) s = fmaf(a2[b * 64 + j], __ldg(W3 + j * 64 + h), s);
        a3[idx] = s;
    }
    __syncthreads();
    if (t < 64) {
        float m = 0.f;
#pragma unroll
        for (int b = 0; b < Bc; b++) m += a3[b * 64 + t];
        m *= 0.125f;
        float v = 0.f;
#pragma unroll
        for (int b = 0; b < Bc; b++) { float dd = a3[b * 64 + t] - m; v = fmaf(dd, dd, v); }
        v *= 0.125f;
        float sc = rsqrtf(v + EPSc) * __ldg(g3 + t);
        float sh = __ldg(be3 + t);
#pragma unroll
        for (int b = 0; b < Bc; b++) {
            float z = (a3[b * 64 + t] - m) * sc + sh;
            a3[b * 64 + t] = z > 0.f ? z : 0.f;
        }
    }
    __syncthreads();
    if (t < 16) {
        int b = t >> 1, c = t & 1;
        float s = __ldg(b4 + c);
        for (int j = 0; j < 64; j++) s = fmaf(a3[b * 64 + j], __ldg(W4 + j * 2 + c), s);
        lg[t] = s;
    }
    __syncthreads();
    if (t < 8) {
        float l0 = lg[t * 2], l1 = lg[t * 2 + 1];
        float m = fmaxf(l0, l1);
        float lse = m + logf(expf(l0 - m) + expf(l1 - m));
        out[t * 2 + 0] = l0 - lse;
        out[t * 2 + 1] = l1 - lse;
    }
}

// ---------------- host driver ----------------
extern "C" void kernel_launch(void* const* d_in, const int* in_sizes, int n_in,
                              void* d_out, int out_size) {
    const float* x    = (const float*)d_in[0];
    const int*   ei   = (const int*)d_in[1];
    int E = in_sizes[1] / 2;
    const int* src = ei;
    const int* dst = ei + E;
    const float* cw0  = (const float*)d_in[3];
    const float* cb0  = (const float*)d_in[4];
    const float* cw1  = (const float*)d_in[5];
    const float* cb1  = (const float*)d_in[6];
    const float* cw2  = (const float*)d_in[7];
    const float* cb2  = (const float*)d_in[8];
    const float* bnhg = (const float*)d_in[9];
    const float* bnhb = (const float*)d_in[10];
    const float* bng  = (const float*)d_in[11];
    const float* bnb  = (const float*)d_in[12];
    const float* w1   = (const float*)d_in[13];
    const float* b1   = (const float*)d_in[14];
    const float* g1   = (const float*)d_in[15];
    const float* be1  = (const float*)d_in[16];
    const float* W2   = (const float*)d_in[17];
    const float* b2   = (const float*)d_in[18];
    const float* g2   = (const float*)d_in[19];
    const float* be2  = (const float*)d_in[20];
    const float* W3   = (const float*)d_in[21];
    const float* b3   = (const float*)d_in[22];
    const float* g3   = (const float*)d_in[23];
    const float* be3  = (const float*)d_in[24];
    const float* W4   = (const float*)d_in[25];
    const float* b4   = (const float*)d_in[26];
    float* out = (float*)d_out;

    void* y1ptr = nullptr;
    cudaGetSymbolAddress(&y1ptr, g_y1);

    cudaStream_t s2 = 0;
    cudaEvent_t evF = 0, evJ = 0;
    bool forked = (cudaStreamCreateWithFlags(&s2, cudaStreamNonBlocking) == cudaSuccess) &&
                  (cudaEventCreateWithFlags(&evF, cudaEventDisableTiming) == cudaSuccess) &&
                  (cudaEventCreateWithFlags(&evJ, cudaEventDisableTiming) == cudaSuccess);
    if (!forked) s2 = 0;

    if (forked) {
        cudaEventRecord(evF, 0);
        cudaStreamWaitEvent(s2, evF, 0);
    }
    cudaMemsetAsync(y1ptr, 0, Bc * HIDc * sizeof(float), s2);
    gemm_kernel<<<GNB, 256, 0, s2>>>(x, w1, bng, bnb);
    if (forked) cudaEventRecord(evJ, s2);

    cudaFuncSetAttribute(cheb_kernel, cudaFuncAttributeMaxDynamicSharedMemorySize,
                         SM_TOT * (int)sizeof(float));
    cheb_kernel<<<16, 1024, SM_TOT * sizeof(float)>>>(src, dst, E,
                                                      cw0, cb0, cw1, cb1, cw2, cb2);

    if (forked) cudaStreamWaitEvent(0, evJ, 0);
    head_kernel<<<1, 256>>>(bnhg, bnhb, b1, g1, be1, W2, b2, g2, be2,
                            W3, b3, g3, be3, W4, b4, out);
}

// round 10
// speedup vs baseline: 4.3350x; 3.0131x over previous
#include <cuda_runtime.h>
#include <math.h>

#define Nn   8000
#define NPc  1000
#define Bc   8
#define Fc   1000
#define HCc  32
#define TRIc 499500
#define HIDc 128
#define EPSc 1e-5f
#define HPLANE (Bc * NPc * HCc)

// ---------------- persistent scratch ----------------
__device__ int    g_bar[32];
__device__ float  g_hbuf[2 * HPLANE];        // h planes (layers 0,1)
__device__ float  g_hv[64 * 20000];          // per-block v-tables: [blk][k][d] float4
__device__ float  g_emb[Bc * 96];
__device__ float  g_y1[Bc * HIDc];

// monotonic N-block barrier (replay-safe, never reset)
__device__ __forceinline__ void gbarN(int slot, int nb) {
    __syncthreads();
    if (threadIdx.x == 0) {
        __threadfence();
        int r = atomicAdd(&g_bar[slot], 1);
        int target = (r / nb + 1) * nb;
        while (atomicAdd(&g_bar[slot], 0) < target) { }
    }
    __syncthreads();
}

// ---------------- smem layout (floats) ----------------
#define SM_A    0          // 4000  (float4[1000])  | aliased pre-pass: deg/cnt/cur
#define SM_B    4000       // 4000  (float4[1000])  | aliased pre-pass: scan
#define SM_EW   8000       // 10000
#define SM_EI   18000      // 5000 (u16 x 10000)
#define SM_ROW  23000      // 1001 -> pad to 1008
#define SM_W    24008      // 640 (5x32x4)
#define SM_POOL 24648      // 64
#define SM_TOT  24712      // 98848 bytes

// ---------------- float4 gather from smem state ----------------
__device__ __forceinline__ float4 gat4(const float4* __restrict__ S,
                                       const float* __restrict__ sEw,
                                       const unsigned short* __restrict__ sEi,
                                       const int* __restrict__ sRow, int d) {
    int i0 = sRow[d], i1 = sRow[d + 1];
    float4 a = make_float4(0.f, 0.f, 0.f, 0.f);
#pragma unroll 2
    for (int i = i0; i < i1; i++) {
        float w = sEw[i];
        float4 sv = S[sEi[i]];
        a.x = fmaf(w, sv.x, a.x);
        a.y = fmaf(w, sv.y, a.y);
        a.z = fmaf(w, sv.z, a.z);
        a.w = fmaf(w, sv.w, a.w);
    }
    return a;
}

// ---------------- one ChebConv layer: node-per-thread, 4 channels ----------------
// mode 0: v_k[d] = cw0[k][d][ch0..ch0+4)   (layer-0 identity input)
// mode 1: v_k[d] = vt4[k*1000 + d]
__device__ void run_layer(int L, int mode, int b, int ch0, int t,
                          float4* sA4, float4* sB4,
                          const int* sRow, const float* sEw, const unsigned short* sEi,
                          const float* __restrict__ vsrc, const float4* __restrict__ vt4,
                          const float* __restrict__ cbL, float* sPool)
{
#define VR(k, d) (mode == 0 ? __ldg((const float4*)(vsrc + (k) * 32000 + (d) * 32 + ch0)) \
                            : __ldcg(vt4 + (k) * 1000 + (d)))
    for (int d = t; d < NPc; d += 512)
        sA4[d] = VR(4, d);
    __syncthreads();
    for (int d = t; d < NPc; d += 512) {
        float4 g = gat4(sA4, sEw, sEi, sRow, d);
        float4 v = VR(3, d);
        sB4[d] = make_float4(fmaf(2.f, g.x, v.x), fmaf(2.f, g.y, v.y),
                             fmaf(2.f, g.z, v.z), fmaf(2.f, g.w, v.w));
    }
    __syncthreads();
    for (int d = t; d < NPc; d += 512) {
        float4 g = gat4(sB4, sEw, sEi, sRow, d);
        float4 v = VR(2, d);
        float4 o = sA4[d];
        sA4[d] = make_float4(fmaf(2.f, g.x, v.x) - o.x, fmaf(2.f, g.y, v.y) - o.y,
                             fmaf(2.f, g.z, v.z) - o.z, fmaf(2.f, g.w, v.w) - o.w);
    }
    __syncthreads();
    for (int d = t; d < NPc; d += 512) {
        float4 g = gat4(sA4, sEw, sEi, sRow, d);
        float4 v = VR(1, d);
        float4 o = sB4[d];
        sB4[d] = make_float4(fmaf(2.f, g.x, v.x) - o.x, fmaf(2.f, g.y, v.y) - o.y,
                             fmaf(2.f, g.z, v.z) - o.z, fmaf(2.f, g.w, v.w) - o.w);
    }
    __syncthreads();
    // final: h = tanh(v0 + G(B) - A + bias)
    float4 bias4 = __ldg((const float4*)(cbL + ch0));
    float4 pool = make_float4(0.f, 0.f, 0.f, 0.f);
    for (int d = t; d < NPc; d += 512) {
        float4 g = gat4(sB4, sEw, sEi, sRow, d);
        float4 v = VR(0, d);
        float4 o = sA4[d];
        float4 h;
        h.x = tanhf(v.x + g.x - o.x + bias4.x);
        h.y = tanhf(v.y + g.y - o.y + bias4.y);
        h.z = tanhf(v.z + g.z - o.z + bias4.z);
        h.w = tanhf(v.w + g.w - o.w + bias4.w);
        pool.x += h.x; pool.y += h.y; pool.z += h.z; pool.w += h.w;
        if (L < 2)
            *(float4*)(g_hbuf + L * HPLANE + b * NPc * HCc + d * HCc + ch0) = h;
    }
    // pool reduce: warp shuffle, then per-warp smem, then direct store (block owns cols)
#pragma unroll
    for (int off = 16; off >= 1; off >>= 1) {
        pool.x += __shfl_down_sync(0xFFFFFFFFu, pool.x, off);
        pool.y += __shfl_down_sync(0xFFFFFFFFu, pool.y, off);
        pool.z += __shfl_down_sync(0xFFFFFFFFu, pool.z, off);
        pool.w += __shfl_down_sync(0xFFFFFFFFu, pool.w, off);
    }
    int wid = t >> 5, lid = t & 31;
    if (lid == 0) *(float4*)(sPool + wid * 4) = pool;
    __syncthreads();
    if (t < 4) {
        float s = 0.f;
#pragma unroll
        for (int w = 0; w < 16; w++) s += sPool[w * 4 + t];
        g_emb[b * 96 + L * 32 + ch0 + t] = s;
    }
    __syncthreads();
#undef VR
}

// ---------------- v-table pass: vt4[k*1000+d] = h[d][:] @ W[k][:, ch0..ch0+4) ----------------
__device__ void vpass(const float* __restrict__ hprev,   // batch base [d][32]
                      const float* __restrict__ cwL,     // (5,32,32)
                      float4* __restrict__ vt4, float* sW, int ch0, int t)
{
    for (int idx = t; idx < 640; idx += 512) {
        int c = idx & 3, j = (idx >> 2) & 31, k = idx >> 7;
        sW[idx] = __ldg(cwL + k * 1024 + j * 32 + ch0 + c);
    }
    __syncthreads();
    for (int d = t; d < NPc; d += 512) {
        float4 hv[8];
#pragma unroll
        for (int q = 0; q < 8; q++)
            hv[q] = __ldcg((const float4*)(hprev + d * 32 + q * 4));
        const float* hh = (const float*)hv;
#pragma unroll
        for (int k = 0; k < 5; k++) {
            float4 acc = make_float4(0.f, 0.f, 0.f, 0.f);
#pragma unroll
            for (int j = 0; j < 32; j++) {
                float hj = hh[j];
                float4 wr = *(const float4*)&sW[k * 128 + j * 4];
                acc.x = fmaf(hj, wr.x, acc.x);
                acc.y = fmaf(hj, wr.y, acc.y);
                acc.z = fmaf(hj, wr.z, acc.z);
                acc.w = fmaf(hj, wr.w, acc.w);
            }
            vt4[k * 1000 + d] = acc;
        }
    }
    __syncthreads();
}

// ---------------- the cheb kernel: 64 blocks x 512 threads ----------------
__global__ void __launch_bounds__(512)
cheb_kernel(const int* __restrict__ src, const int* __restrict__ dst, int E,
            const float* __restrict__ cw0, const float* __restrict__ cb0,
            const float* __restrict__ cw1, const float* __restrict__ cb1,
            const float* __restrict__ cw2, const float* __restrict__ cb2)
{
    extern __shared__ float sm[];
    float4* sA4 = (float4*)(sm + SM_A);
    float4* sB4 = (float4*)(sm + SM_B);
    float* sEw  = sm + SM_EW;
    unsigned short* sEi = (unsigned short*)(sm + SM_EI);
    int* sRow   = (int*)(sm + SM_ROW);
    float* sW   = sm + SM_W;
    float* sPool= sm + SM_POOL;
    // CSR-build scratch aliased over sA/sB (dead until first pass)
    int* pDeg  = (int*)(sm + SM_A);
    int* pCnt  = (int*)(sm + SM_A) + 1000;
    int* pCur  = (int*)(sm + SM_A) + 2000;
    int* pScan = (int*)(sm + SM_B);

    const int t = threadIdx.x, blk = blockIdx.x;
    const int b = blk >> 3, r = blk & 7;
    const int ch0 = r * 4;
    const int EB = E / Bc;
    const int e0 = b * EB;
    float4* vt4 = (float4*)(g_hv + blk * 20000);

    // ---- in-block CSR build for batch b ----
    for (int i = t; i < NPc; i += 512) { pDeg[i] = 0; pCnt[i] = 0; }
    __syncthreads();
    for (int e = e0 + t; e < e0 + EB; e += 512) {
        atomicAdd(&pDeg[__ldg(src + e) - b * NPc], 1);
        atomicAdd(&pCnt[__ldg(dst + e) - b * NPc], 1);
    }
    __syncthreads();
    {   // exclusive scan of pCnt (2 elems/thread)
        int c0 = (2 * t < NPc) ? pCnt[2 * t] : 0;
        int c1 = (2 * t + 1 < NPc) ? pCnt[2 * t + 1] : 0;
        pScan[t] = c0 + c1;
        __syncthreads();
        for (int off = 1; off < 512; off <<= 1) {
            int v = (t >= off) ? pScan[t - off] : 0;
            __syncthreads();
            pScan[t] += v;
            __syncthreads();
        }
        int pref = (t > 0) ? pScan[t - 1] : 0;
        if (2 * t < NPc)     { sRow[2 * t] = pref;          pCur[2 * t] = pref; }
        if (2 * t + 1 < NPc) { sRow[2 * t + 1] = pref + c0; pCur[2 * t + 1] = pref + c0; }
        if (t == 0) sRow[NPc] = pScan[511];
    }
    __syncthreads();
    for (int e = e0 + t; e < e0 + EB; e += 512) {
        int s_ = __ldg(src + e) - b * NPc;
        int d_ = __ldg(dst + e) - b * NPc;
        int ds = pDeg[s_], dd = pDeg[d_];
        float w = (ds > 0 && dd > 0) ? -rsqrtf((float)ds) * rsqrtf((float)dd) : 0.f;
        int pos = atomicAdd(&pCur[d_], 1);
        sEw[pos] = w;
        sEi[pos] = (unsigned short)s_;
    }
    __syncthreads();   // scratch dead; sA/sB reusable

    // ---- layer 0 (v-tables = cw0 planes) ----
    run_layer(0, 0, b, ch0, t, sA4, sB4, sRow, sEw, sEi, cw0, nullptr, cb0, sPool);

    __threadfence();
    gbarN(b * 2 + 0, 8);
    vpass(g_hbuf + 0 * HPLANE + b * NPc * HCc, cw1, vt4, sW, ch0, t);
    run_layer(1, 1, b, ch0, t, sA4, sB4, sRow, sEw, sEi, nullptr, vt4, cb1, sPool);

    __threadfence();
    gbarN(b * 2 + 1, 8);
    vpass(g_hbuf + 1 * HPLANE + b * NPc * HCc, cw2, vt4, sW, ch0, t);
    run_layer(2, 1, b, ch0, t, sA4, sB4, sRow, sEw, sEi, nullptr, vt4, cb2, sPool);
}

// ---------------- GEMM kernel: fused triu+fbn + W1 stream (double-buffered) ----------------
#define GNB   396
#define GCH   256
#define GNCH  ((TRIc + GCH - 1) / GCH)   // 1952

__device__ __forceinline__ void triidx(int f, int& i, int& j) {
    float disc = 3996001.0f - 8.0f * (float)f;
    float sq = sqrtf(fmaxf(disc, 0.f));
    i = (int)((1999.0f - sq) * 0.5f);
    i = max(0, min(i, Fc - 2));
    while (i + 1 <= Fc - 2 && (((long long)(i + 1) * (1999 - (i + 1))) >> 1) <= (long long)f) i++;
    while (i > 0 && (((long long)i * (1999 - i)) >> 1) > (long long)f) i--;
    int Si = (int)(((long long)i * (1999 - i)) >> 1);
    j = i + 1 + (f - Si);
}

__global__ void __launch_bounds__(256, 3)
gemm_kernel(const float* __restrict__ x, const float* __restrict__ W1,
            const float* __restrict__ bng, const float* __restrict__ bnb)
{
    __shared__ float sfb[2][GCH * 8];
    __shared__ float sred[4096];
    int t = threadIdx.x, wp = t >> 5, l = t & 31;
    float acc[Bc][4];
#pragma unroll
    for (int b = 0; b < Bc; b++)
#pragma unroll
        for (int q = 0; q < 4; q++) acc[b][q] = 0.f;

    {
        int f = blockIdx.x * GCH + t;
        float res[Bc];
        if (f < TRIc) {
            int i, j; triidx(f, i, j);
            float v[Bc]; float m = 0.f;
#pragma unroll
            for (int b = 0; b < Bc; b++) {
                v[b] = __ldg(x + ((size_t)(b * Fc + i) * Fc + j));
                m += v[b];
            }
            m *= 0.125f;
            float var = 0.f;
#pragma unroll
            for (int b = 0; b < Bc; b++) { float dd = v[b] - m; var = fmaf(dd, dd, var); }
            var *= 0.125f;
            float sc = rsqrtf(var + EPSc) * __ldg(bng + f);
            float sh = __ldg(bnb + f);
#pragma unroll
            for (int b = 0; b < Bc; b++) res[b] = (v[b] - m) * sc + sh;
        } else {
#pragma unroll
            for (int b = 0; b < Bc; b++) res[b] = 0.f;
        }
        *(float4*)&sfb[0][t * 8]     = make_float4(res[0], res[1], res[2], res[3]);
        *(float4*)&sfb[0][t * 8 + 4] = make_float4(res[4], res[5], res[6], res[7]);
    }
    __syncthreads();

    int p = 0;
    for (int c = blockIdx.x; c < GNCH; c += GNB) {
        int cn = c + GNB;
        bool hasNext = (cn < GNCH);
        float xv[Bc]; float bgv = 0.f, bbv = 0.f; bool val = false;
        if (hasNext) {
            int fN = cn * GCH + t;
            val = (fN < TRIc);
            if (val) {
                int i, j; triidx(fN, i, j);
#pragma unroll
                for (int b = 0; b < Bc; b++)
                    xv[b] = __ldg(x + ((size_t)(b * Fc + i) * Fc + j));
                bgv = __ldg(bng + fN);
                bbv = __ldg(bnb + fN);
            }
        }
        {
            int fbase = c * GCH;
            int r0 = wp * 32;
            const float* buf = sfb[p];
#pragma unroll 2
            for (int rb = 0; rb < 32; rb += 4) {
                float4 w[4];
#pragma unroll
                for (int u = 0; u < 4; u++) {
                    int f2 = min(fbase + r0 + rb + u, TRIc - 1);
                    w[u] = __ldcs((const float4*)(W1 + (size_t)f2 * HIDc + l * 4));
                }
#pragma unroll
                for (int u = 0; u < 4; u++) {
                    int fl = r0 + rb + u;
                    float4 f0 = *(const float4*)&buf[fl * 8];
                    float4 f1 = *(const float4*)&buf[fl * 8 + 4];
                    acc[0][0] = fmaf(f0.x, w[u].x, acc[0][0]); acc[0][1] = fmaf(f0.x, w[u].y, acc[0][1]);
                    acc[0][2] = fmaf(f0.x, w[u].z, acc[0][2]); acc[0][3] = fmaf(f0.x, w[u].w, acc[0][3]);
                    acc[1][0] = fmaf(f0.y, w[u].x, acc[1][0]); acc[1][1] = fmaf(f0.y, w[u].y, acc[1][1]);
                    acc[1][2] = fmaf(f0.y, w[u].z, acc[1][2]); acc[1][3] = fmaf(f0.y, w[u].w, acc[1][3]);
                    acc[2][0] = fmaf(f0.z, w[u].x, acc[2][0]); acc[2][1] = fmaf(f0.z, w[u].y, acc[2][1]);
                    acc[2][2] = fmaf(f0.z, w[u].z, acc[2][2]); acc[2][3] = fmaf(f0.z, w[u].w, acc[2][3]);
                    acc[3][0] = fmaf(f0.w, w[u].x, acc[3][0]); acc[3][1] = fmaf(f0.w, w[u].y, acc[3][1]);
                    acc[3][2] = fmaf(f0.w, w[u].z, acc[3][2]); acc[3][3] = fmaf(f0.w, w[u].w, acc[3][3]);
                    acc[4][0] = fmaf(f1.x, w[u].x, acc[4][0]); acc[4][1] = fmaf(f1.x, w[u].y, acc[4][1]);
                    acc[4][2] = fmaf(f1.x, w[u].z, acc[4][2]); acc[4][3] = fmaf(f1.x, w[u].w, acc[4][3]);
                    acc[5][0] = fmaf(f1.y, w[u].x, acc[5][0]); acc[5][1] = fmaf(f1.y, w[u].y, acc[5][1]);
                    acc[5][2] = fmaf(f1.y, w[u].z, acc[5][2]); acc[5][3] = fmaf(f1.y, w[u].w, acc[5][3]);
                    acc[6][0] = fmaf(f1.z, w[u].x, acc[6][0]); acc[6][1] = fmaf(f1.z, w[u].y, acc[6][1]);
                    acc[6][2] = fmaf(f1.z, w[u].z, acc[6][2]); acc[6][3] = fmaf(f1.z, w[u].w, acc[6][3]);
                    acc[7][0] = fmaf(f1.w, w[u].x, acc[7][0]); acc[7][1] = fmaf(f1.w, w[u].y, acc[7][1]);
                    acc[7][2] = fmaf(f1.w, w[u].z, acc[7][2]); acc[7][3] = fmaf(f1.w, w[u].w, acc[7][3]);
                }
            }
        }
        if (hasNext) {
            float res[Bc];
            if (val) {
                float m = 0.f;
#pragma unroll
                for (int b = 0; b < Bc; b++) m += xv[b];
                m *= 0.125f;
                float var = 0.f;
#pragma unroll
                for (int b = 0; b < Bc; b++) { float dd = xv[b] - m; var = fmaf(dd, dd, var); }
                var *= 0.125f;
                float sc = rsqrtf(var + EPSc) * bgv;
#pragma unroll
                for (int b = 0; b < Bc; b++) res[b] = (xv[b] - m) * sc + bbv;
            } else {
#pragma unroll
                for (int b = 0; b < Bc; b++) res[b] = 0.f;
            }
            *(float4*)&sfb[p ^ 1][t * 8]     = make_float4(res[0], res[1], res[2], res[3]);
            *(float4*)&sfb[p ^ 1][t * 8 + 4] = make_float4(res[4], res[5], res[6], res[7]);
        }
        __syncthreads();
        p ^= 1;
    }

    for (int half = 4; half >= 1; half >>= 1) {
        if (wp >= half && wp < 2 * half) {
            float* reg = sred + (wp - half) * 1024;
#pragma unroll
            for (int b = 0; b < Bc; b++)
                *(float4*)&reg[b * HIDc + l * 4] =
                    make_float4(acc[b][0], acc[b][1], acc[b][2], acc[b][3]);
        }
        __syncthreads();
        if (wp < half) {
            float* reg = sred + wp * 1024;
#pragma unroll
            for (int b = 0; b < Bc; b++) {
                float4 z = *(const float4*)&reg[b * HIDc + l * 4];
                acc[b][0] += z.x; acc[b][1] += z.y; acc[b][2] += z.z; acc[b][3] += z.w;
            }
        }
        __syncthreads();
    }
    if (wp == 0) {
#pragma unroll
        for (int b = 0; b < Bc; b++)
#pragma unroll
            for (int q = 0; q < 4; q++)
                atomicAdd(&g_y1[b * HIDc + l * 4 + q], acc[b][q]);
    }
}

// ---------------- head ----------------
__global__ void head_kernel(const float* __restrict__ bnhg, const float* __restrict__ bnhb,
                            const float* __restrict__ b1,
                            const float* __restrict__ g1, const float* __restrict__ be1,
                            const float* __restrict__ W2, const float* __restrict__ b2,
                            const float* __restrict__ g2, const float* __restrict__ be2,
                            const float* __restrict__ W3, const float* __restrict__ b3,
                            const float* __restrict__ g3, const float* __restrict__ be3,
                            const float* __restrict__ W4, const float* __restrict__ b4,
                            float* __restrict__ out) {
    __shared__ float a1[8 * 128];
    __shared__ float a2[8 * 64];
    __shared__ float a3[8 * 64];
    __shared__ float lg[16];
    int t = threadIdx.x;

    if (t < 96) {
        float e[Bc]; float m = 0.f;
#pragma unroll
        for (int b = 0; b < Bc; b++) { e[b] = __ldcg(&g_emb[b * 96 + t]) * (1.f / (float)NPc); m += e[b]; }
        m *= 0.125f;
        float v = 0.f;
#pragma unroll
        for (int b = 0; b < Bc; b++) { float dd = e[b] - m; v = fmaf(dd, dd, v); }
        v *= 0.125f;
        float sc = rsqrtf(v + EPSc) * __ldg(bnhg + t);
        float sh = __ldg(bnhb + t);
#pragma unroll
        for (int b = 0; b < Bc; b++) out[16 + b * 96 + t] = (e[b] - m) * sc + sh;
    }

    for (int idx = t; idx < 1024; idx += 256) a1[idx] = __ldcg(&g_y1[idx]) + __ldg(&b1[idx & 127]);
    __syncthreads();
    if (t < 128) {
        float m = 0.f;
#pragma unroll
        for (int b = 0; b < Bc; b++) m += a1[b * 128 + t];
        m *= 0.125f;
        float v = 0.f;
#pragma unroll
        for (int b = 0; b < Bc; b++) { float dd = a1[b * 128 + t] - m; v = fmaf(dd, dd, v); }
        v *= 0.125f;
        float sc = rsqrtf(v + EPSc) * __ldg(g1 + t);
        float sh = __ldg(be1 + t);
#pragma unroll
        for (int b = 0; b < Bc; b++) {
            float z = (a1[b * 128 + t] - m) * sc + sh;
            a1[b * 128 + t] = z > 0.f ? z : 0.f;
        }
    }
    __syncthreads();
    for (int idx = t; idx < 512; idx += 256) {
        int b = idx >> 6, h = idx & 63;
        float s = __ldg(b2 + h);
        for (int j = 0; j < 128; j++) s = fmaf(a1[b * 128 + j], __ldg(W2 + j * 64 + h), s);
        a2[idx] = s;
    }
    __syncthreads();
    if (t < 64) {
        float m = 0.f;
#pragma unroll
        for (int b = 0; b < Bc; b++) m += a2[b * 64 + t];
        m *= 0.125f;
        float v = 0.f;
#pragma unroll
        for (int b = 0; b < Bc; b++) { float dd = a2[b * 64 + t] - m; v = fmaf(dd, dd, v); }
        v *= 0.125f;
        float sc = rsqrtf(v + EPSc) * __ldg(g2 + t);
        float sh = __ldg(be2 + t);
#pragma unroll
        for (int b = 0; b < Bc; b++) {
            float z = (a2[b * 64 + t] - m) * sc + sh;
            a2[b * 64 + t] = z > 0.f ? z : 0.f;
        }
    }
    __syncthreads();
    for (int idx = t; idx < 512; idx += 256) {
        int b = idx >> 6, h = idx & 63;
        float s = __ldg(b3 + h);
        for (int j = 0; j < 64; j++) s = fmaf(a2[b * 64 + j], __ldg(W3 + j * 64 + h), s);
        a3[idx] = s;
    }
    __syncthreads();
    if (t < 64) {
        float m = 0.f;
#pragma unroll
        for (int b = 0; b < Bc; b++) m += a3[b * 64 + t];
        m *= 0.125f;
        float v = 0.f;
#pragma unroll
        for (int b = 0; b < Bc; b++) { float dd = a3[b * 64 + t] - m; v = fmaf(dd, dd, v); }
        v *= 0.125f;
        float sc = rsqrtf(v + EPSc) * __ldg(g3 + t);
        float sh = __ldg(be3 + t);
#pragma unroll
        for (int b = 0; b < Bc; b++) {
            float z = (a3[b * 64 + t] - m) * sc + sh;
            a3[b * 64 + t] = z > 0.f ? z : 0.f;
        }
    }
    __syncthreads();
    if (t < 16) {
        int b = t >> 1, c = t & 1;
        float s = __ldg(b4 + c);
        for (int j = 0; j < 64; j++) s = fmaf(a3[b * 64 + j], __ldg(W4 + j * 2 + c), s);
        lg[t] = s;
    }
    __syncthreads();
    if (t < 8) {
        float l0 = lg[t * 2], l1 = lg[t * 2 + 1];
        float m = fmaxf(l0, l1);
        float lse = m + logf(expf(l0 - m) + expf(l1 - m));
        out[t * 2 + 0] = l0 - lse;
        out[t * 2 + 1] = l1 - lse;
    }
}

// ---------------- host driver ----------------
extern "C" void kernel_launch(void* const* d_in, const int* in_sizes, int n_in,
                              void* d_out, int out_size) {
    const float* x    = (const float*)d_in[0];
    const int*   ei   = (const int*)d_in[1];
    int E = in_sizes[1] / 2;
    const int* src = ei;
    const int* dst = ei + E;
    const float* cw0  = (const float*)d_in[3];
    const float* cb0  = (const float*)d_in[4];
    const float* cw1  = (const float*)d_in[5];
    const float* cb1  = (const float*)d_in[6];
    const float* cw2  = (const float*)d_in[7];
    const float* cb2  = (const float*)d_in[8];
    const float* bnhg = (const float*)d_in[9];
    const float* bnhb = (const float*)d_in[10];
    const float* bng  = (const float*)d_in[11];
    const float* bnb  = (const float*)d_in[12];
    const float* w1   = (const float*)d_in[13];
    const float* b1   = (const float*)d_in[14];
    const float* g1   = (const float*)d_in[15];
    const float* be1  = (const float*)d_in[16];
    const float* W2   = (const float*)d_in[17];
    const float* b2   = (const float*)d_in[18];
    const float* g2   = (const float*)d_in[19];
    const float* be2  = (const float*)d_in[20];
    const float* W3   = (const float*)d_in[21];
    const float* b3   = (const float*)d_in[22];
    const float* g3   = (const float*)d_in[23];
    const float* be3  = (const float*)d_in[24];
    const float* W4   = (const float*)d_in[25];
    const float* b4   = (const float*)d_in[26];
    float* out = (float*)d_out;

    void* y1ptr = nullptr;
    cudaGetSymbolAddress(&y1ptr, g_y1);

    cudaStream_t s2 = 0;
    cudaEvent_t evF = 0, evJ = 0;
    bool forked = (cudaStreamCreateWithFlags(&s2, cudaStreamNonBlocking) == cudaSuccess) &&
                  (cudaEventCreateWithFlags(&evF, cudaEventDisableTiming) == cudaSuccess) &&
                  (cudaEventCreateWithFlags(&evJ, cudaEventDisableTiming) == cudaSuccess);
    if (!forked) s2 = 0;

    if (forked) {
        cudaEventRecord(evF, 0);
        cudaStreamWaitEvent(s2, evF, 0);
    }

    // cheb first (small grid, big smem) so its blocks get placed immediately
    cudaFuncSetAttribute(cheb_kernel, cudaFuncAttributeMaxDynamicSharedMemorySize,
                         SM_TOT * (int)sizeof(float));
    cheb_kernel<<<64, 512, SM_TOT * sizeof(float)>>>(src, dst, E,
                                                     cw0, cb0, cw1, cb1, cw2, cb2);

    cudaMemsetAsync(y1ptr, 0, Bc * HIDc * sizeof(float), s2);
    gemm_kernel<<<GNB, 256, 0, s2>>>(x, w1, bng, bnb);
    if (forked) cudaEventRecord(evJ, s2);

    if (forked) cudaStreamWaitEvent(0, evJ, 0);
    head_kernel<<<1, 256>>>(bnhg, bnhb, b1, g1, be1, W2, b2, g2, be2,
                            W3, b3, g3, be3, W4, b4, out);
}